// round 2
// baseline (speedup 1.0000x reference)
#include <cuda_runtime.h>
#include <math.h>

// Problem constants
#define B_   2
#define M_   8192
#define H_   8
#define D_   64
#define HD   512
#define F3   1536
#define NSEG 16

// ---------------- device scratch (no allocations allowed) ----------------
__device__ int      g_perm[M_];
__device__ int      g_dval[M_];
__device__ unsigned g_flags[16384];
__device__ unsigned g_psum[16384];
__device__ float    g_x[B_ * M_ * D_];          // 4 MB   : sum over heads of q
__device__ float    g_weff[F3 * D_];            // 0.4 MB : head-reduced w_qkv (incl. 1/H)
__device__ float    g_qkv[(size_t)B_ * M_ * F3];// 100 MB : projected q/k/v
__device__ float    g_attn[(size_t)B_ * M_ * HD];// 33 MB : attention out (orig token order)

// ---------------- Hilbert permutation ----------------
__global__ void k_zero_flags() {
    int i = blockIdx.x * 256 + threadIdx.x;
    if (i < 16384) g_flags[i] = 0u;
}

__global__ void k_hilbert() {
    int i = blockIdx.x * 256 + threadIdx.x;
    if (i >= M_) return;
    int x = i & 127, y = i >> 7;   // side = 128
    int d = 0;
    for (int s = 64; s > 0; s >>= 1) {
        int rx = (x & s) ? 1 : 0;
        int ry = (y & s) ? 1 : 0;
        d += s * s * ((3 * rx) ^ ry);
        if (ry == 0) {
            if (rx == 1) { x = s - 1 - x; y = s - 1 - y; }
            int t = x; x = y; y = t;
        }
    }
    g_dval[i] = d;
    g_flags[d] = 1u;   // d values are unique -> no race
}

__global__ void k_scan() {   // exclusive prefix sum of g_flags (16384), 1 block x 256
    __shared__ unsigned part[256];
    int t = threadIdx.x;
    unsigned s = 0;
    for (int i = 0; i < 64; i++) s += g_flags[t * 64 + i];
    part[t] = s;
    __syncthreads();
    if (t == 0) {
        unsigned run = 0;
        for (int i = 0; i < 256; i++) { unsigned v = part[i]; part[i] = run; run += v; }
    }
    __syncthreads();
    unsigned run = part[t];
    for (int i = 0; i < 64; i++) {
        unsigned v = g_flags[t * 64 + i];
        g_psum[t * 64 + i] = run;
        run += v;
    }
}

__global__ void k_rank() {
    int i = blockIdx.x * 256 + threadIdx.x;
    if (i >= M_) return;
    g_perm[g_psum[g_dval[i]]] = i;   // perm[rank] = token
}

// ---------------- head-reduced weight + head-sum of q ----------------
__global__ void k_weff(const float* __restrict__ w_qkv) {
    int e = blockIdx.x * 256 + threadIdx.x;
    if (e >= F3 * D_) return;
    int f = e >> 6, d = e & 63;
    float s = 0.f;
#pragma unroll
    for (int h = 0; h < 8; h++) s += w_qkv[f * HD + h * 64 + d];
    g_weff[e] = 0.125f * s;   // fold the 1/H of the mean in here
}

__global__ void k_mean(const float* __restrict__ q) {
    int e = blockIdx.x * 256 + threadIdx.x;     // e = row*64 + d
    if (e >= B_ * M_ * D_) return;
    int row = e >> 6, d = e & 63;
    const float* p = q + (size_t)row * HD + d;
    float s = 0.f;
#pragma unroll
    for (int h = 0; h < 8; h++) s += p[h * 64];
    g_x[e] = s;
}

// ---------------- generic tiled GEMM: C[Mr,Nr] = A[Mr,Kr] * B[Nr,Kr]^T ----------------
// 64x64 block tile, 16x16 threads, 4x4 micro-tile. Mr,Nr,Kr all multiples of 64.
__global__ void k_gemm_nt(const float* __restrict__ A, const float* __restrict__ Bm,
                          float* __restrict__ C, int Mr, int Nr, int Kr) {
    __shared__ float As[64][65];
    __shared__ float Bs[64][65];
    int row0 = blockIdx.y * 64, col0 = blockIdx.x * 64;
    int tx = threadIdx.x, ty = threadIdx.y;
    int tid = ty * 16 + tx;
    float acc[4][4] = {};
    for (int k0 = 0; k0 < Kr; k0 += 64) {
#pragma unroll
        for (int i = 0; i < 16; i++) {
            int e = tid + i * 256;
            int r = e >> 6, c = e & 63;
            As[r][c] = A[(size_t)(row0 + r) * Kr + k0 + c];
            Bs[r][c] = Bm[(size_t)(col0 + r) * Kr + k0 + c];
        }
        __syncthreads();
#pragma unroll 16
        for (int k = 0; k < 64; k++) {
            float av[4], bv[4];
#pragma unroll
            for (int i = 0; i < 4; i++) av[i] = As[ty * 4 + i][k];
#pragma unroll
            for (int j = 0; j < 4; j++) bv[j] = Bs[tx * 4 + j][k];
#pragma unroll
            for (int i = 0; i < 4; i++)
#pragma unroll
                for (int j = 0; j < 4; j++) acc[i][j] += av[i] * bv[j];
        }
        __syncthreads();
    }
#pragma unroll
    for (int i = 0; i < 4; i++)
#pragma unroll
        for (int j = 0; j < 4; j++)
            C[(size_t)(row0 + ty * 4 + i) * Nr + col0 + tx * 4 + j] = acc[i][j];
}

// ---------------- fused segment attention ----------------
// grid: 2048 blocks = B(2) * seg(16) * head(8) * qchunk(8); 256 threads.
// Each block: 64 queries vs full 512 keys of its segment, one head.
// smem: scores 64x516 + Q 64x65 + KV 64x65 + invl[64] = 165632 B.
#define SMEM_ATTN 165632
__global__ void k_attn(const float* __restrict__ qkv, float* __restrict__ attn) {
    extern __shared__ float sm[];
    float* S_sh = sm;                       // 64 * 516
    float* Qs   = sm + 64 * 516;            // 64 * 65
    float* KVs  = Qs + 64 * 65;             // 64 * 65
    float* invl = KVs + 64 * 65;            // 64

    int tid = threadIdx.x;
    int bid = blockIdx.x;
    int qc  = bid & 7;
    int h   = (bid >> 3) & 7;
    int seg = (bid >> 6) & 15;
    int b   = bid >> 10;
    size_t base = (size_t)b * M_ * F3;
    int q0 = seg * 512 + qc * 64;

    // ---- load Q tile (gather via perm), pre-scaled by D^-0.5 = 0.125 ----
    for (int e = tid; e < 4096; e += 256) {
        int qi = e >> 6, dd = e & 63;
        int tok = g_perm[q0 + qi];
        Qs[qi * 65 + dd] = 0.125f * qkv[base + (size_t)tok * F3 + h * 64 + dd];
    }

    int tq = tid >> 4;    // 0..15  -> 4 query rows
    int tk = tid & 15;    // 0..15  -> 4 key cols / 4 d cols

    // ---- scores: S = Q K^T ----
    for (int kt = 0; kt < 8; kt++) {
        __syncthreads();
        for (int e = tid; e < 4096; e += 256) {
            int kj = e >> 6, dd = e & 63;
            int tok = g_perm[seg * 512 + kt * 64 + kj];
            KVs[kj * 65 + dd] = qkv[base + (size_t)tok * F3 + 512 + h * 64 + dd];
        }
        __syncthreads();
        float acc[4][4] = {};
#pragma unroll 8
        for (int d = 0; d < 64; d++) {
            float qv[4], kv[4];
#pragma unroll
            for (int i = 0; i < 4; i++) qv[i] = Qs[(tq * 4 + i) * 65 + d];
#pragma unroll
            for (int j = 0; j < 4; j++) kv[j] = KVs[(tk * 4 + j) * 65 + d];
#pragma unroll
            for (int i = 0; i < 4; i++)
#pragma unroll
                for (int j = 0; j < 4; j++) acc[i][j] += qv[i] * kv[j];
        }
#pragma unroll
        for (int i = 0; i < 4; i++)
#pragma unroll
            for (int j = 0; j < 4; j++)
                S_sh[(tq * 4 + i) * 516 + kt * 64 + tk * 4 + j] = acc[i][j];
    }
    __syncthreads();

    // ---- softmax (store exp(s-m); keep 1/l per row) ----
    int warp = tid >> 5, lane = tid & 31;
    for (int r = warp; r < 64; r += 8) {
        float mx = -3.4e38f;
        for (int t = lane; t < 512; t += 32) mx = fmaxf(mx, S_sh[r * 516 + t]);
#pragma unroll
        for (int o = 16; o; o >>= 1) mx = fmaxf(mx, __shfl_xor_sync(0xffffffffu, mx, o));
        float l = 0.f;
        for (int t = lane; t < 512; t += 32) {
            float ev = __expf(S_sh[r * 516 + t] - mx);
            S_sh[r * 516 + t] = ev;
            l += ev;
        }
#pragma unroll
        for (int o = 16; o; o >>= 1) l += __shfl_xor_sync(0xffffffffu, l, o);
        if (lane == 0) invl[r] = 1.f / l;
    }

    // ---- out = P V ----
    float oacc[4][4] = {};
    for (int vt = 0; vt < 8; vt++) {
        __syncthreads();
        for (int e = tid; e < 4096; e += 256) {
            int vj = e >> 6, dd = e & 63;
            int tok = g_perm[seg * 512 + vt * 64 + vj];
            KVs[vj * 65 + dd] = qkv[base + (size_t)tok * F3 + 1024 + h * 64 + dd];
        }
        __syncthreads();
#pragma unroll 4
        for (int t = 0; t < 64; t++) {
            float pv[4], vv[4];
#pragma unroll
            for (int i = 0; i < 4; i++) pv[i] = S_sh[(tq * 4 + i) * 516 + vt * 64 + t];
#pragma unroll
            for (int j = 0; j < 4; j++) vv[j] = KVs[t * 65 + tk * 4 + j];
#pragma unroll
            for (int i = 0; i < 4; i++)
#pragma unroll
                for (int j = 0; j < 4; j++) oacc[i][j] += pv[i] * vv[j];
        }
    }

    // ---- scatter back to original token order, normalized ----
#pragma unroll
    for (int i = 0; i < 4; i++) {
        int qi = tq * 4 + i;
        int tok = g_perm[q0 + qi];
        float il = invl[qi];
        size_t ob = ((size_t)b * M_ + tok) * HD + h * 64 + tk * 4;
#pragma unroll
        for (int j = 0; j < 4; j++) attn[ob + j] = oacc[i][j] * il;
    }
}

// ---------------- launch ----------------
extern "C" void kernel_launch(void* const* d_in, const int* in_sizes, int n_in,
                              void* d_out, int out_size) {
    const float* q     = (const float*)d_in[0];
    // d_in[1] = k, d_in[2] = v : unused by the reference computation
    const float* w_qkv = (const float*)d_in[3];
    const float* w_out = (const float*)d_in[4];
    float* out = (float*)d_out;

    void *p_x, *p_weff, *p_qkv, *p_attn;
    cudaGetSymbolAddress(&p_x,    g_x);
    cudaGetSymbolAddress(&p_weff, g_weff);
    cudaGetSymbolAddress(&p_qkv,  g_qkv);
    cudaGetSymbolAddress(&p_attn, g_attn);

    cudaFuncSetAttribute(k_attn, cudaFuncAttributeMaxDynamicSharedMemorySize, SMEM_ATTN);

    // Hilbert permutation (cheap, deterministic, recomputed each replay)
    k_zero_flags<<<64, 256>>>();
    k_hilbert<<<32, 256>>>();
    k_scan<<<1, 256>>>();
    k_rank<<<32, 256>>>();

    // head-reduced projection
    k_weff<<<(F3 * D_ + 255) / 256, 256>>>(w_qkv);
    k_mean<<<(B_ * M_ * D_ + 255) / 256, 256>>>(q);

    // GEMM1: qkv[16384,1536] = x[16384,64] * weff[1536,64]^T
    {
        dim3 blk(16, 16), grd(F3 / 64, (B_ * M_) / 64);
        k_gemm_nt<<<grd, blk>>>((const float*)p_x, (const float*)p_weff,
                                (float*)p_qkv, B_ * M_, F3, D_);
    }

    // fused segment attention
    k_attn<<<B_ * NSEG * H_ * 8, 256, SMEM_ATTN>>>((const float*)p_qkv, (float*)p_attn);

    // GEMM2: out[16384,512] = attn[16384,512] * w_out[512,512]^T
    {
        dim3 blk(16, 16), grd(HD / 64, (B_ * M_) / 64);
        k_gemm_nt<<<grd, blk>>>((const float*)p_attn, w_out, out, B_ * M_, HD, HD);
    }
}

// round 4
// speedup vs baseline: 2.2862x; 2.2862x over previous
#include <cuda_runtime.h>
#include <math.h>

// Problem constants
#define B_   2
#define M_   8192
#define H_   8
#define D_   64
#define HD   512
#define F3   1536
#define NSEG 16

// ---------------- device scratch (no allocations allowed) ----------------
__device__ int      g_perm[M_];
__device__ int      g_dval[M_];
__device__ unsigned g_flags[16384];
__device__ unsigned g_psum[16384];
__device__ float    g_x[B_ * M_ * D_];           // head-sum of q
__device__ float    g_weff[F3 * D_];             // head-reduced w_qkv (incl. 1/H)
__device__ float    g_qkv[(size_t)B_ * M_ * F3]; // projected q/k/v
__device__ float    g_attn[(size_t)B_ * M_ * HD];// attention out (orig token order)

// ---------------- Hilbert permutation ----------------
__global__ void k_zero_flags() {
    int i = blockIdx.x * 256 + threadIdx.x;
    if (i < 16384) g_flags[i] = 0u;
}

__global__ void k_hilbert() {
    int i = blockIdx.x * 256 + threadIdx.x;
    if (i >= M_) return;
    int x = i & 127, y = i >> 7;   // side = 128
    int d = 0;
    for (int s = 64; s > 0; s >>= 1) {
        int rx = (x & s) ? 1 : 0;
        int ry = (y & s) ? 1 : 0;
        d += s * s * ((3 * rx) ^ ry);
        if (ry == 0) {
            if (rx == 1) { x = s - 1 - x; y = s - 1 - y; }
            int t = x; x = y; y = t;
        }
    }
    g_dval[i] = d;
    g_flags[d] = 1u;   // d unique -> no race
}

__global__ void k_scan() {   // exclusive prefix sum of g_flags (16384)
    __shared__ unsigned part[256];
    int t = threadIdx.x;
    unsigned s = 0;
    for (int i = 0; i < 64; i++) s += g_flags[t * 64 + i];
    part[t] = s;
    __syncthreads();
    if (t == 0) {
        unsigned run = 0;
        for (int i = 0; i < 256; i++) { unsigned v = part[i]; part[i] = run; run += v; }
    }
    __syncthreads();
    unsigned run = part[t];
    for (int i = 0; i < 64; i++) {
        unsigned v = g_flags[t * 64 + i];
        g_psum[t * 64 + i] = run;
        run += v;
    }
}

__global__ void k_rank() {
    int i = blockIdx.x * 256 + threadIdx.x;
    if (i >= M_) return;
    g_perm[g_psum[g_dval[i]]] = i;   // perm[rank] = token
}

// ---------------- head-reduced weight + head-sum of q ----------------
__global__ void k_weff(const float* __restrict__ w_qkv) {
    int e = blockIdx.x * 256 + threadIdx.x;
    if (e >= F3 * D_) return;
    int f = e >> 6, d = e & 63;
    float s = 0.f;
#pragma unroll
    for (int h = 0; h < 8; h++) s += w_qkv[f * HD + h * 64 + d];
    g_weff[e] = 0.125f * s;   // fold 1/H of the mean
}

__global__ void k_mean(const float* __restrict__ q) {
    int e = blockIdx.x * 256 + threadIdx.x;
    if (e >= B_ * M_ * D_) return;
    int row = e >> 6, d = e & 63;
    const float* p = q + (size_t)row * HD + d;
    float s = 0.f;
#pragma unroll
    for (int h = 0; h < 8; h++) s += p[h * 64];
    g_x[e] = s;
}

// =====================================================================
// GEMM: C[Mr,Nr] = A[Mr,Kr] * B[Nr,Kr]^T
// Tile 128m x 64n x 64k, 256 threads, 8x4 micro-tile.
// Smem tiles stored k-major with XOR swizzle (float4 granularity):
//   element (m,k) -> As[k*128 + (((m>>2) ^ ((k>>2)&15))<<2) + (m&3)]
//   element (n,k) -> Bs[k*64  + (((n>>2) ^ ((k>>2)&15))<<2) + (n&3)]
// Compute loads are LDS.128, conflict-free / broadcast.
// =====================================================================
__global__ __launch_bounds__(256, 3)
void k_gemm_nt(const float* __restrict__ A, const float* __restrict__ Bm,
               float* __restrict__ C, int Mr, int Nr, int Kr) {
    extern __shared__ float smg[];
    float* As = smg;            // 64 * 128
    float* Bs = smg + 8192;     // 64 * 64
    float4* As4 = (float4*)As;
    float4* Bs4 = (float4*)Bs;

    int tid = threadIdx.x;
    int tm = tid >> 4;          // 0..15 -> 8 m rows
    int tn = tid & 15;          // 0..15 -> 4 n cols
    int row0 = blockIdx.y * 128, col0 = blockIdx.x * 64;

    float acc[8][4] = {};

    for (int k0 = 0; k0 < Kr; k0 += 64) {
        // ---- load A tile (128 x 64) transposed+swizzled ----
#pragma unroll
        for (int i = 0; i < 8; i++) {
            int e = 4 * (tid + 256 * i);
            int m = e >> 6, kk = e & 63;
            float4 v = *(const float4*)&A[(size_t)(row0 + m) * Kr + k0 + kk];
            int col = (((m >> 2) ^ ((kk >> 2) & 15)) << 2) + (m & 3);
            As[(kk + 0) * 128 + col] = v.x;
            As[(kk + 1) * 128 + col] = v.y;
            As[(kk + 2) * 128 + col] = v.z;
            As[(kk + 3) * 128 + col] = v.w;
        }
        // ---- load B tile (64 x 64) transposed+swizzled ----
#pragma unroll
        for (int i = 0; i < 4; i++) {
            int e = 4 * (tid + 256 * i);
            int n = e >> 6, kk = e & 63;
            float4 v = *(const float4*)&Bm[(size_t)(col0 + n) * Kr + k0 + kk];
            int col = (((n >> 2) ^ ((kk >> 2) & 15)) << 2) + (n & 3);
            Bs[(kk + 0) * 64 + col] = v.x;
            Bs[(kk + 1) * 64 + col] = v.y;
            Bs[(kk + 2) * 64 + col] = v.z;
            Bs[(kk + 3) * 64 + col] = v.w;
        }
        __syncthreads();

#pragma unroll
        for (int k4 = 0; k4 < 16; k4++) {
            int s = k4;    // (k>>2)&15
#pragma unroll
            for (int j = 0; j < 4; j++) {
                int k = k4 * 4 + j;
                float4 a0 = As4[k * 32 + ((2 * tm) ^ s)];
                float4 a1 = As4[k * 32 + ((2 * tm + 1) ^ s)];
                float4 b  = Bs4[k * 16 + (tn ^ s)];
                float av[8] = {a0.x, a0.y, a0.z, a0.w, a1.x, a1.y, a1.z, a1.w};
                float bv[4] = {b.x, b.y, b.z, b.w};
#pragma unroll
                for (int ii = 0; ii < 8; ii++)
#pragma unroll
                    for (int jj = 0; jj < 4; jj++) acc[ii][jj] += av[ii] * bv[jj];
            }
        }
        __syncthreads();
    }

#pragma unroll
    for (int i = 0; i < 8; i++) {
        float4 o = {acc[i][0], acc[i][1], acc[i][2], acc[i][3]};
        *(float4*)&C[(size_t)(row0 + tm * 8 + i) * Nr + col0 + tn * 4] = o;
    }
}

// =====================================================================
// Fused segment attention, flash-style online softmax.
// grid: 2048 = B(2)*seg(16)*head(8)*qchunk(8); 256 threads.
// Block: 64 queries vs 512 keys (8 tiles of 64), one head.
// smem: Qs/Ks (d-major swizzled 64x64), Vs (t-major 64x64), Ps (m-major 64x64),
//       m/l/fac[64] -> 66304 B -> 3 blocks/SM.
// =====================================================================
#define SMEM_ATTN (4 * 4096 * 4 + 3 * 64 * 4)
__global__ __launch_bounds__(256, 3)
void k_attn(const float* __restrict__ qkv, float* __restrict__ attn) {
    extern __shared__ float sm[];
    float* Qs   = sm;               // [d][m] swizzled
    float* Ks   = sm + 4096;        // [d][n] swizzled
    float* Vs   = sm + 8192;        // [t][n] natural
    float* Ps   = sm + 12288;       // [m][t] natural
    float* m_sh = sm + 16384;
    float* l_sh = m_sh + 64;
    float* fac  = l_sh + 64;
    float4* Qs4 = (float4*)Qs;
    float4* Ks4 = (float4*)Ks;

    int tid = threadIdx.x;
    int bid = blockIdx.x;
    int qc  = bid & 7;
    int h   = (bid >> 3) & 7;
    int seg = (bid >> 6) & 15;
    int b   = bid >> 10;
    size_t base = (size_t)b * M_ * F3;
    int q0 = seg * 512 + qc * 64;

    int tq = tid >> 4;    // 0..15 -> 4 query rows
    int tk = tid & 15;    // 0..15 -> 4 key/d cols
    int warp = tid >> 5, lane = tid & 31;

    // ---- load Q tile transposed+swizzled, pre-scaled by D^-0.5 ----
#pragma unroll
    for (int i = 0; i < 4; i++) {
        int e = 4 * (tid + 256 * i);
        int mi = e >> 6, dd = e & 63;
        int tok = g_perm[q0 + mi];
        float4 v = *(const float4*)&qkv[base + (size_t)tok * F3 + h * 64 + dd];
        int col = (((mi >> 2) ^ ((dd >> 2) & 15)) << 2) + (mi & 3);
        Qs[(dd + 0) * 64 + col] = 0.125f * v.x;
        Qs[(dd + 1) * 64 + col] = 0.125f * v.y;
        Qs[(dd + 2) * 64 + col] = 0.125f * v.z;
        Qs[(dd + 3) * 64 + col] = 0.125f * v.w;
    }
    if (tid < 64) { m_sh[tid] = -1e30f; l_sh[tid] = 0.f; }

    float oacc[4][4] = {};

    for (int kt = 0; kt < 8; kt++) {
        // ---- load K tile transposed+swizzled ----
#pragma unroll
        for (int i = 0; i < 4; i++) {
            int e = 4 * (tid + 256 * i);
            int nj = e >> 6, dd = e & 63;
            int tok = g_perm[seg * 512 + kt * 64 + nj];
            float4 v = *(const float4*)&qkv[base + (size_t)tok * F3 + 512 + h * 64 + dd];
            int col = (((nj >> 2) ^ ((dd >> 2) & 15)) << 2) + (nj & 3);
            Ks[(dd + 0) * 64 + col] = v.x;
            Ks[(dd + 1) * 64 + col] = v.y;
            Ks[(dd + 2) * 64 + col] = v.z;
            Ks[(dd + 3) * 64 + col] = v.w;
        }
        __syncthreads();

        // ---- S tile = Q K^T ----
        float acc[4][4] = {};
#pragma unroll
        for (int d4 = 0; d4 < 16; d4++) {
            int s = d4;
#pragma unroll
            for (int j = 0; j < 4; j++) {
                int d = d4 * 4 + j;
                float4 a = Qs4[d * 16 + (tq ^ s)];
                float4 bq = Ks4[d * 16 + (tk ^ s)];
                float av[4] = {a.x, a.y, a.z, a.w};
                float bv[4] = {bq.x, bq.y, bq.z, bq.w};
#pragma unroll
                for (int ii = 0; ii < 4; ii++)
#pragma unroll
                    for (int jj = 0; jj < 4; jj++) acc[ii][jj] += av[ii] * bv[jj];
            }
        }
#pragma unroll
        for (int ii = 0; ii < 4; ii++) {
            float4 o = {acc[ii][0], acc[ii][1], acc[ii][2], acc[ii][3]};
            *(float4*)&Ps[(tq * 4 + ii) * 64 + tk * 4] = o;
        }
        __syncthreads();

        // ---- online softmax update (8 warps x 8 rows) ----
        for (int r = warp; r < 64; r += 8) {
            float v0 = Ps[r * 64 + lane];
            float v1 = Ps[r * 64 + 32 + lane];
            float mx = fmaxf(v0, v1);
#pragma unroll
            for (int o = 16; o; o >>= 1) mx = fmaxf(mx, __shfl_xor_sync(0xffffffffu, mx, o));
            float mo = m_sh[r];
            float mn = fmaxf(mo, mx);
            float f  = __expf(mo - mn);
            float e0 = __expf(v0 - mn);
            float e1 = __expf(v1 - mn);
            Ps[r * 64 + lane]      = e0;
            Ps[r * 64 + 32 + lane] = e1;
            float ts = e0 + e1;
#pragma unroll
            for (int o = 16; o; o >>= 1) ts += __shfl_xor_sync(0xffffffffu, ts, o);
            if (lane == 0) { l_sh[r] = l_sh[r] * f + ts; m_sh[r] = mn; fac[r] = f; }
        }
        __syncthreads();

        // ---- rescale accumulator + load V tile ----
        float fr[4];
#pragma unroll
        for (int ii = 0; ii < 4; ii++) fr[ii] = fac[tq * 4 + ii];
#pragma unroll
        for (int ii = 0; ii < 4; ii++)
#pragma unroll
            for (int jj = 0; jj < 4; jj++) oacc[ii][jj] *= fr[ii];

#pragma unroll
        for (int i = 0; i < 4; i++) {
            int e = 4 * (tid + 256 * i);
            int tj = e >> 6, dd = e & 63;
            int tok = g_perm[seg * 512 + kt * 64 + tj];
            float4 v = *(const float4*)&qkv[base + (size_t)tok * F3 + 1024 + h * 64 + dd];
            *(float4*)&Vs[tj * 64 + dd] = v;
        }
        __syncthreads();

        // ---- oacc += P V ----
#pragma unroll
        for (int t4 = 0; t4 < 16; t4++) {
            float pv[4][4];
#pragma unroll
            for (int ii = 0; ii < 4; ii++) {
                float4 p = *(const float4*)&Ps[(tq * 4 + ii) * 64 + t4 * 4];
                pv[ii][0] = p.x; pv[ii][1] = p.y; pv[ii][2] = p.z; pv[ii][3] = p.w;
            }
#pragma unroll
            for (int j = 0; j < 4; j++) {
                float4 v = *(const float4*)&Vs[(t4 * 4 + j) * 64 + tk * 4];
                float vv[4] = {v.x, v.y, v.z, v.w};
#pragma unroll
                for (int ii = 0; ii < 4; ii++)
#pragma unroll
                    for (int jj = 0; jj < 4; jj++) oacc[ii][jj] += pv[ii][j] * vv[jj];
            }
        }
        __syncthreads();
    }

    // ---- normalize + scatter to original token order ----
#pragma unroll
    for (int ii = 0; ii < 4; ii++) {
        int qi = tq * 4 + ii;
        int tok = g_perm[q0 + qi];
        float il = 1.f / l_sh[qi];
        float4 o = {oacc[ii][0] * il, oacc[ii][1] * il, oacc[ii][2] * il, oacc[ii][3] * il};
        *(float4*)&attn[((size_t)b * M_ + tok) * HD + h * 64 + tk * 4] = o;
    }
}

// ---------------- launch ----------------
extern "C" void kernel_launch(void* const* d_in, const int* in_sizes, int n_in,
                              void* d_out, int out_size) {
    const float* q     = (const float*)d_in[0];
    const float* w_qkv = (const float*)d_in[3];
    const float* w_out = (const float*)d_in[4];
    float* out = (float*)d_out;

    void *p_x, *p_weff, *p_qkv, *p_attn;
    cudaGetSymbolAddress(&p_x,    g_x);
    cudaGetSymbolAddress(&p_weff, g_weff);
    cudaGetSymbolAddress(&p_qkv,  g_qkv);
    cudaGetSymbolAddress(&p_attn, g_attn);

    cudaFuncSetAttribute(k_attn, cudaFuncAttributeMaxDynamicSharedMemorySize, SMEM_ATTN);
    cudaFuncSetAttribute(k_gemm_nt, cudaFuncAttributeMaxDynamicSharedMemorySize, 49152);

    // Hilbert permutation
    k_zero_flags<<<64, 256>>>();
    k_hilbert<<<32, 256>>>();
    k_scan<<<1, 256>>>();
    k_rank<<<32, 256>>>();

    // head-reduced projection inputs
    k_weff<<<(F3 * D_ + 255) / 256, 256>>>(w_qkv);
    k_mean<<<(B_ * M_ * D_ + 255) / 256, 256>>>(q);

    // GEMM1: qkv[16384,1536] = x[16384,64] * weff[1536,64]^T
    {
        dim3 grd(F3 / 64, (B_ * M_) / 128);
        k_gemm_nt<<<grd, 256, 49152>>>((const float*)p_x, (const float*)p_weff,
                                       (float*)p_qkv, B_ * M_, F3, D_);
    }

    // fused segment attention
    k_attn<<<B_ * NSEG * H_ * 8, 256, SMEM_ATTN>>>((const float*)p_qkv, (float*)p_attn);

    // GEMM2: out[16384,512] = attn[16384,512] * w_out[512,512]^T
    {
        dim3 grd(HD / 64, (B_ * M_) / 128);
        k_gemm_nt<<<grd, 256, 49152>>>((const float*)p_attn, w_out, out, B_ * M_, HD, HD);
    }
}

// round 5
// speedup vs baseline: 2.3922x; 1.0463x over previous
#include <cuda_runtime.h>
#include <math.h>

// Problem constants
#define B_   2
#define M_   8192
#define H_   8
#define D_   64
#define HD   512
#define F3   1536
#define NSEG 16

// ---------------- f32x2 packed helpers (sm_103a FFMA2 path) ----------------
__device__ __forceinline__ unsigned long long pk2(float v) {
    unsigned long long r;
    asm("mov.b64 %0, {%1, %1};" : "=l"(r) : "f"(v));
    return r;
}
__device__ __forceinline__ void fma2(unsigned long long& c, unsigned long long a, unsigned long long b) {
    asm("fma.rn.f32x2 %0, %1, %2, %0;" : "+l"(c) : "l"(a), "l"(b));
}
__device__ __forceinline__ void mul2(unsigned long long& d, unsigned long long a) {
    asm("mul.rn.f32x2 %0, %1, %0;" : "+l"(d) : "l"(a));
}
__device__ __forceinline__ void upk2(unsigned long long v, float& lo, float& hi) {
    asm("mov.b64 {%0, %1}, %2;" : "=f"(lo), "=f"(hi) : "l"(v));
}

// ---------------- device scratch (no allocations allowed) ----------------
__device__ int      g_perm[M_];
__device__ int      g_dval[M_];
__device__ unsigned g_flags[16384];
__device__ unsigned g_psum[16384];
__device__ float    g_x[B_ * M_ * D_];
__device__ float    g_weff[F3 * D_];
__device__ float    g_qkv[(size_t)B_ * M_ * F3];
__device__ float    g_attn[(size_t)B_ * M_ * HD];

// ---------------- Hilbert permutation ----------------
__global__ void k_zero_flags() {
    int i = blockIdx.x * 256 + threadIdx.x;
    if (i < 16384) g_flags[i] = 0u;
}

__global__ void k_hilbert() {
    int i = blockIdx.x * 256 + threadIdx.x;
    if (i >= M_) return;
    int x = i & 127, y = i >> 7;
    int d = 0;
    for (int s = 64; s > 0; s >>= 1) {
        int rx = (x & s) ? 1 : 0;
        int ry = (y & s) ? 1 : 0;
        d += s * s * ((3 * rx) ^ ry);
        if (ry == 0) {
            if (rx == 1) { x = s - 1 - x; y = s - 1 - y; }
            int t = x; x = y; y = t;
        }
    }
    g_dval[i] = d;
    g_flags[d] = 1u;
}

__global__ void k_scan() {
    __shared__ unsigned part[256];
    int t = threadIdx.x;
    unsigned s = 0;
    for (int i = 0; i < 64; i++) s += g_flags[t * 64 + i];
    part[t] = s;
    __syncthreads();
    if (t == 0) {
        unsigned run = 0;
        for (int i = 0; i < 256; i++) { unsigned v = part[i]; part[i] = run; run += v; }
    }
    __syncthreads();
    unsigned run = part[t];
    for (int i = 0; i < 64; i++) {
        unsigned v = g_flags[t * 64 + i];
        g_psum[t * 64 + i] = run;
        run += v;
    }
}

__global__ void k_rank() {
    int i = blockIdx.x * 256 + threadIdx.x;
    if (i >= M_) return;
    g_perm[g_psum[g_dval[i]]] = i;
}

// ---------------- head-reduced weight + head-sum of q ----------------
__global__ void k_weff(const float* __restrict__ w_qkv) {
    int e = blockIdx.x * 256 + threadIdx.x;
    if (e >= F3 * D_) return;
    int f = e >> 6, d = e & 63;
    float s = 0.f;
#pragma unroll
    for (int h = 0; h < 8; h++) s += w_qkv[f * HD + h * 64 + d];
    g_weff[e] = 0.125f * s;
}

__global__ void k_mean(const float* __restrict__ q) {
    int e = blockIdx.x * 256 + threadIdx.x;
    if (e >= B_ * M_ * D_) return;
    int row = e >> 6, d = e & 63;
    const float* p = q + (size_t)row * HD + d;
    float s = 0.f;
#pragma unroll
    for (int h = 0; h < 8; h++) s += p[h * 64];
    g_x[e] = s;
}

// =====================================================================
// GEMM: C[Mr,Nr] = A[Mr,Kr] * B[Nr,Kr]^T  (FFMA2 inner loop)
// Tile 128m x 64n x 64k, 256 threads, 8x4 micro-tile, m-paired.
// =====================================================================
__global__ __launch_bounds__(256, 3)
void k_gemm_nt(const float* __restrict__ A, const float* __restrict__ Bm,
               float* __restrict__ C, int Mr, int Nr, int Kr) {
    extern __shared__ float smg[];
    float* As = smg;            // 64 * 128
    float* Bs = smg + 8192;     // 64 * 64
    const ulonglong2* As2 = (const ulonglong2*)As;
    const float4*     Bs4 = (const float4*)Bs;

    int tid = threadIdx.x;
    int tm = tid >> 4;
    int tn = tid & 15;
    int row0 = blockIdx.y * 128, col0 = blockIdx.x * 64;

    unsigned long long acc2[4][4];   // [m-pair][n]
#pragma unroll
    for (int i = 0; i < 4; i++)
#pragma unroll
        for (int j = 0; j < 4; j++) acc2[i][j] = 0ull;

    for (int k0 = 0; k0 < Kr; k0 += 64) {
#pragma unroll
        for (int i = 0; i < 8; i++) {
            int e = 4 * (tid + 256 * i);
            int m = e >> 6, kk = e & 63;
            float4 v = *(const float4*)&A[(size_t)(row0 + m) * Kr + k0 + kk];
            int col = (((m >> 2) ^ ((kk >> 2) & 15)) << 2) + (m & 3);
            As[(kk + 0) * 128 + col] = v.x;
            As[(kk + 1) * 128 + col] = v.y;
            As[(kk + 2) * 128 + col] = v.z;
            As[(kk + 3) * 128 + col] = v.w;
        }
#pragma unroll
        for (int i = 0; i < 4; i++) {
            int e = 4 * (tid + 256 * i);
            int n = e >> 6, kk = e & 63;
            float4 v = *(const float4*)&Bm[(size_t)(col0 + n) * Kr + k0 + kk];
            int col = (((n >> 2) ^ ((kk >> 2) & 15)) << 2) + (n & 3);
            Bs[(kk + 0) * 64 + col] = v.x;
            Bs[(kk + 1) * 64 + col] = v.y;
            Bs[(kk + 2) * 64 + col] = v.z;
            Bs[(kk + 3) * 64 + col] = v.w;
        }
        __syncthreads();

#pragma unroll
        for (int k4 = 0; k4 < 16; k4++) {
            int s = k4;
#pragma unroll
            for (int j = 0; j < 4; j++) {
                int k = k4 * 4 + j;
                ulonglong2 a0 = As2[k * 32 + ((2 * tm) ^ s)];     // m pairs 0,1
                ulonglong2 a1 = As2[k * 32 + ((2 * tm + 1) ^ s)]; // m pairs 2,3
                float4 b = Bs4[k * 16 + (tn ^ s)];
                unsigned long long bp[4] = {pk2(b.x), pk2(b.y), pk2(b.z), pk2(b.w)};
                unsigned long long ap[4] = {a0.x, a0.y, a1.x, a1.y};
#pragma unroll
                for (int ii = 0; ii < 4; ii++)
#pragma unroll
                    for (int jj = 0; jj < 4; jj++) fma2(acc2[ii][jj], ap[ii], bp[jj]);
            }
        }
        __syncthreads();
    }

#pragma unroll
    for (int p = 0; p < 4; p++) {
        float lo[4], hi[4];
#pragma unroll
        for (int j = 0; j < 4; j++) upk2(acc2[p][j], lo[j], hi[j]);
        float4 o0 = {lo[0], lo[1], lo[2], lo[3]};
        float4 o1 = {hi[0], hi[1], hi[2], hi[3]};
        *(float4*)&C[(size_t)(row0 + tm * 8 + 2 * p)     * Nr + col0 + tn * 4] = o0;
        *(float4*)&C[(size_t)(row0 + tm * 8 + 2 * p + 1) * Nr + col0 + tn * 4] = o1;
    }
}

// =====================================================================
// Fused segment attention, flash-style, FFMA2 inner loops.
// grid: 2048 = B*seg*head*qchunk; 256 threads; smem 66304 B -> 3 blocks/SM.
// =====================================================================
#define SMEM_ATTN (4 * 4096 * 4 + 3 * 64 * 4)
__global__ __launch_bounds__(256, 3)
void k_attn(const float* __restrict__ qkv, float* __restrict__ attn) {
    extern __shared__ float sm[];
    float* Qs   = sm;               // [d][m] swizzled
    float* Ks   = sm + 4096;        // [d][n] swizzled
    float* Vs   = sm + 8192;        // [t][n] natural
    float* Ps   = sm + 12288;       // [m][t] natural
    float* m_sh = sm + 16384;
    float* l_sh = m_sh + 64;
    float* fac  = l_sh + 64;
    const ulonglong2* Qs2 = (const ulonglong2*)Qs;
    const float4*     Ks4 = (const float4*)Ks;
    const ulonglong2* Vs2 = (const ulonglong2*)Vs;
    const float4*     Ps4 = (const float4*)Ps;

    int tid = threadIdx.x;
    int bid = blockIdx.x;
    int qc  = bid & 7;
    int h   = (bid >> 3) & 7;
    int seg = (bid >> 6) & 15;
    int b   = bid >> 10;
    size_t base = (size_t)b * M_ * F3;
    int q0 = seg * 512 + qc * 64;

    int tq = tid >> 4;
    int tk = tid & 15;
    int warp = tid >> 5, lane = tid & 31;

    // ---- load Q tile transposed+swizzled, pre-scaled by D^-0.5 ----
#pragma unroll
    for (int i = 0; i < 4; i++) {
        int e = 4 * (tid + 256 * i);
        int mi = e >> 6, dd = e & 63;
        int tok = g_perm[q0 + mi];
        float4 v = *(const float4*)&qkv[base + (size_t)tok * F3 + h * 64 + dd];
        int col = (((mi >> 2) ^ ((dd >> 2) & 15)) << 2) + (mi & 3);
        Qs[(dd + 0) * 64 + col] = 0.125f * v.x;
        Qs[(dd + 1) * 64 + col] = 0.125f * v.y;
        Qs[(dd + 2) * 64 + col] = 0.125f * v.z;
        Qs[(dd + 3) * 64 + col] = 0.125f * v.w;
    }
    if (tid < 64) { m_sh[tid] = -1e30f; l_sh[tid] = 0.f; }

    unsigned long long oacc2[4][2];   // [ii][d-pair]
#pragma unroll
    for (int i = 0; i < 4; i++) { oacc2[i][0] = 0ull; oacc2[i][1] = 0ull; }

    for (int kt = 0; kt < 8; kt++) {
        // ---- load K tile transposed+swizzled ----
#pragma unroll
        for (int i = 0; i < 4; i++) {
            int e = 4 * (tid + 256 * i);
            int nj = e >> 6, dd = e & 63;
            int tok = g_perm[seg * 512 + kt * 64 + nj];
            float4 v = *(const float4*)&qkv[base + (size_t)tok * F3 + 512 + h * 64 + dd];
            int col = (((nj >> 2) ^ ((dd >> 2) & 15)) << 2) + (nj & 3);
            Ks[(dd + 0) * 64 + col] = v.x;
            Ks[(dd + 1) * 64 + col] = v.y;
            Ks[(dd + 2) * 64 + col] = v.z;
            Ks[(dd + 3) * 64 + col] = v.w;
        }
        __syncthreads();

        // ---- S tile = Q K^T (m-paired FFMA2) ----
        unsigned long long sacc[2][4];
#pragma unroll
        for (int p = 0; p < 2; p++)
#pragma unroll
            for (int j = 0; j < 4; j++) sacc[p][j] = 0ull;
#pragma unroll
        for (int d4 = 0; d4 < 16; d4++) {
            int s = d4;
#pragma unroll
            for (int j = 0; j < 4; j++) {
                int d = d4 * 4 + j;
                ulonglong2 qa = Qs2[d * 16 + (tq ^ s)];   // m pairs
                float4 kb = Ks4[d * 16 + (tk ^ s)];
                unsigned long long kp[4] = {pk2(kb.x), pk2(kb.y), pk2(kb.z), pk2(kb.w)};
#pragma unroll
                for (int jj = 0; jj < 4; jj++) { fma2(sacc[0][jj], qa.x, kp[jj]); fma2(sacc[1][jj], qa.y, kp[jj]); }
            }
        }
#pragma unroll
        for (int p = 0; p < 2; p++) {
            float lo[4], hi[4];
#pragma unroll
            for (int j = 0; j < 4; j++) upk2(sacc[p][j], lo[j], hi[j]);
            float4 o0 = {lo[0], lo[1], lo[2], lo[3]};
            float4 o1 = {hi[0], hi[1], hi[2], hi[3]};
            *(float4*)&Ps[(tq * 4 + 2 * p)     * 64 + tk * 4] = o0;
            *(float4*)&Ps[(tq * 4 + 2 * p + 1) * 64 + tk * 4] = o1;
        }
        __syncthreads();

        // ---- online softmax update ----
        for (int r = warp; r < 64; r += 8) {
            float v0 = Ps[r * 64 + lane];
            float v1 = Ps[r * 64 + 32 + lane];
            float mx = fmaxf(v0, v1);
#pragma unroll
            for (int o = 16; o; o >>= 1) mx = fmaxf(mx, __shfl_xor_sync(0xffffffffu, mx, o));
            float mo = m_sh[r];
            float mn = fmaxf(mo, mx);
            float f  = __expf(mo - mn);
            float e0 = __expf(v0 - mn);
            float e1 = __expf(v1 - mn);
            Ps[r * 64 + lane]      = e0;
            Ps[r * 64 + 32 + lane] = e1;
            float ts = e0 + e1;
#pragma unroll
            for (int o = 16; o; o >>= 1) ts += __shfl_xor_sync(0xffffffffu, ts, o);
            if (lane == 0) { l_sh[r] = l_sh[r] * f + ts; m_sh[r] = mn; fac[r] = f; }
        }
        __syncthreads();

        // ---- rescale accumulator (packed) + load V tile ----
#pragma unroll
        for (int ii = 0; ii < 4; ii++) {
            unsigned long long fp = pk2(fac[tq * 4 + ii]);
            mul2(oacc2[ii][0], fp);
            mul2(oacc2[ii][1], fp);
        }

#pragma unroll
        for (int i = 0; i < 4; i++) {
            int e = 4 * (tid + 256 * i);
            int tj = e >> 6, dd = e & 63;
            int tok = g_perm[seg * 512 + kt * 64 + tj];
            float4 v = *(const float4*)&qkv[base + (size_t)tok * F3 + 1024 + h * 64 + dd];
            *(float4*)&Vs[tj * 64 + dd] = v;
        }
        __syncthreads();

        // ---- oacc += P V (d-paired FFMA2) ----
#pragma unroll
        for (int t4 = 0; t4 < 16; t4++) {
            float4 pf[4];
#pragma unroll
            for (int ii = 0; ii < 4; ii++) pf[ii] = Ps4[(tq * 4 + ii) * 16 + t4];
#pragma unroll
            for (int j = 0; j < 4; j++) {
                ulonglong2 v2 = Vs2[(t4 * 4 + j) * 16 + tk];   // d pairs
                float pv[4] = {pf[0].x, pf[1].x, pf[2].x, pf[3].x};
                // select component j of each pf
                if (j == 1) { pv[0] = pf[0].y; pv[1] = pf[1].y; pv[2] = pf[2].y; pv[3] = pf[3].y; }
                if (j == 2) { pv[0] = pf[0].z; pv[1] = pf[1].z; pv[2] = pf[2].z; pv[3] = pf[3].z; }
                if (j == 3) { pv[0] = pf[0].w; pv[1] = pf[1].w; pv[2] = pf[2].w; pv[3] = pf[3].w; }
#pragma unroll
                for (int ii = 0; ii < 4; ii++) {
                    unsigned long long pp = pk2(pv[ii]);
                    fma2(oacc2[ii][0], pp, v2.x);
                    fma2(oacc2[ii][1], pp, v2.y);
                }
            }
        }
        __syncthreads();
    }

    // ---- normalize + scatter to original token order ----
#pragma unroll
    for (int ii = 0; ii < 4; ii++) {
        int qi = tq * 4 + ii;
        int tok = g_perm[q0 + qi];
        float il = 1.f / l_sh[qi];
        float o0, o1, o2, o3;
        upk2(oacc2[ii][0], o0, o1);
        upk2(oacc2[ii][1], o2, o3);
        float4 o = {o0 * il, o1 * il, o2 * il, o3 * il};
        *(float4*)&attn[((size_t)b * M_ + tok) * HD + h * 64 + tk * 4] = o;
    }
}

// ---------------- launch ----------------
extern "C" void kernel_launch(void* const* d_in, const int* in_sizes, int n_in,
                              void* d_out, int out_size) {
    const float* q     = (const float*)d_in[0];
    const float* w_qkv = (const float*)d_in[3];
    const float* w_out = (const float*)d_in[4];
    float* out = (float*)d_out;

    void *p_x, *p_weff, *p_qkv, *p_attn;
    cudaGetSymbolAddress(&p_x,    g_x);
    cudaGetSymbolAddress(&p_weff, g_weff);
    cudaGetSymbolAddress(&p_qkv,  g_qkv);
    cudaGetSymbolAddress(&p_attn, g_attn);

    cudaFuncSetAttribute(k_attn, cudaFuncAttributeMaxDynamicSharedMemorySize, SMEM_ATTN);
    cudaFuncSetAttribute(k_gemm_nt, cudaFuncAttributeMaxDynamicSharedMemorySize, 49152);

    k_zero_flags<<<64, 256>>>();
    k_hilbert<<<32, 256>>>();
    k_scan<<<1, 256>>>();
    k_rank<<<32, 256>>>();

    k_weff<<<(F3 * D_ + 255) / 256, 256>>>(w_qkv);
    k_mean<<<(B_ * M_ * D_ + 255) / 256, 256>>>(q);

    // GEMM1: qkv[16384,1536] = x[16384,64] * weff[1536,64]^T
    {
        dim3 grd(F3 / 64, (B_ * M_) / 128);
        k_gemm_nt<<<grd, 256, 49152>>>((const float*)p_x, (const float*)p_weff,
                                       (float*)p_qkv, B_ * M_, F3, D_);
    }

    // fused segment attention
    k_attn<<<B_ * NSEG * H_ * 8, 256, SMEM_ATTN>>>((const float*)p_qkv, (float*)p_attn);

    // GEMM2: out[16384,512] = attn[16384,512] * w_out[512,512]^T
    {
        dim3 grd(HD / 64, (B_ * M_) / 128);
        k_gemm_nt<<<grd, 256, 49152>>>((const float*)p_attn, w_out, out, B_ * M_, HD, HD);
    }
}

// round 6
// speedup vs baseline: 2.5695x; 1.0741x over previous
#include <cuda_runtime.h>
#include <math.h>

// Problem constants
#define B_   2
#define M_   8192
#define H_   8
#define D_   64
#define HD   512
#define F3   1536
#define NSEG 16

// ---------------- f32x2 packed helpers (sm_103a FFMA2 path) ----------------
__device__ __forceinline__ unsigned long long pk2(float v) {
    unsigned long long r;
    asm("mov.b64 %0, {%1, %1};" : "=l"(r) : "f"(v));
    return r;
}
__device__ __forceinline__ void fma2(unsigned long long& c, unsigned long long a, unsigned long long b) {
    asm("fma.rn.f32x2 %0, %1, %2, %0;" : "+l"(c) : "l"(a), "l"(b));
}
__device__ __forceinline__ void mul2(unsigned long long& d, unsigned long long a) {
    asm("mul.rn.f32x2 %0, %1, %0;" : "+l"(d) : "l"(a));
}
__device__ __forceinline__ void upk2(unsigned long long v, float& lo, float& hi) {
    asm("mov.b64 {%0, %1}, %2;" : "=f"(lo), "=f"(hi) : "l"(v));
}

// swizzled column for a 128-element row (half-split slot layout):
// element e -> slot g=e>>2; slot' = (g&16) | ((g&15)^s); col = slot'*4 + (e&3)
__device__ __forceinline__ int swcol128(int e, int s) {
    int g = e >> 2;
    int c4 = (g & 16) | ((g & 15) ^ s);
    return c4 * 4 + (e & 3);
}

// ---------------- device scratch (no allocations allowed) ----------------
__device__ int      g_perm[M_];
__device__ int      g_dval[M_];
__device__ unsigned g_flags[16384];
__device__ unsigned g_psum[16384];
__device__ float    g_x[B_ * M_ * D_];
__device__ float    g_weff[F3 * D_];
__device__ float    g_qkv[(size_t)B_ * M_ * F3];
__device__ float    g_attn[(size_t)B_ * M_ * HD];

// ---------------- Hilbert permutation ----------------
__global__ void k_zero_flags() {
    int i = blockIdx.x * 256 + threadIdx.x;
    if (i < 16384) g_flags[i] = 0u;
}

__global__ void k_hilbert() {
    int i = blockIdx.x * 256 + threadIdx.x;
    if (i >= M_) return;
    int x = i & 127, y = i >> 7;
    int d = 0;
    for (int s = 64; s > 0; s >>= 1) {
        int rx = (x & s) ? 1 : 0;
        int ry = (y & s) ? 1 : 0;
        d += s * s * ((3 * rx) ^ ry);
        if (ry == 0) {
            if (rx == 1) { x = s - 1 - x; y = s - 1 - y; }
            int t = x; x = y; y = t;
        }
    }
    g_dval[i] = d;
    g_flags[d] = 1u;
}

__global__ void k_scan() {
    __shared__ unsigned part[256];
    int t = threadIdx.x;
    unsigned s = 0;
    for (int i = 0; i < 64; i++) s += g_flags[t * 64 + i];
    part[t] = s;
    __syncthreads();
    if (t == 0) {
        unsigned run = 0;
        for (int i = 0; i < 256; i++) { unsigned v = part[i]; part[i] = run; run += v; }
    }
    __syncthreads();
    unsigned run = part[t];
    for (int i = 0; i < 64; i++) {
        unsigned v = g_flags[t * 64 + i];
        g_psum[t * 64 + i] = run;
        run += v;
    }
}

__global__ void k_rank() {
    int i = blockIdx.x * 256 + threadIdx.x;
    if (i >= M_) return;
    g_perm[g_psum[g_dval[i]]] = i;
}

// ---------------- head-reduced weight + head-sum of q ----------------
__global__ void k_weff(const float* __restrict__ w_qkv) {
    int e = blockIdx.x * 256 + threadIdx.x;
    if (e >= F3 * D_) return;
    int f = e >> 6, d = e & 63;
    float s = 0.f;
#pragma unroll
    for (int h = 0; h < 8; h++) s += w_qkv[f * HD + h * 64 + d];
    g_weff[e] = 0.125f * s;
}

__global__ void k_mean(const float* __restrict__ q) {
    int e = blockIdx.x * 256 + threadIdx.x;
    if (e >= B_ * M_ * D_) return;
    int row = e >> 6, d = e & 63;
    const float* p = q + (size_t)row * HD + d;
    float s = 0.f;
#pragma unroll
    for (int h = 0; h < 8; h++) s += p[h * 64];
    g_x[e] = s;
}

// =====================================================================
// GEMM: C[Mr,Nr] = A[Mr,Kr] * B[Nr,Kr]^T   (FFMA2, 8x8 micro-tile)
// Tile 128m x 128n x 64k, 256 threads.
// Thread (tm,tn): m in {4tm..4tm+3, 64+4tm..+3}, n likewise with tn.
// =====================================================================
__global__ __launch_bounds__(256, 2)
void k_gemm_nt(const float* __restrict__ A, const float* __restrict__ Bm,
               float* __restrict__ C, int Mr, int Nr, int Kr) {
    extern __shared__ float smg[];
    float* As = smg;            // 64 rows x 128
    float* Bs = smg + 8192;     // 64 rows x 128
    const ulonglong2* As2 = (const ulonglong2*)As;
    const float4*     Bs4 = (const float4*)Bs;

    int tid = threadIdx.x;
    int tm = tid >> 4;
    int tn = tid & 15;
    int row0 = blockIdx.y * 128, col0 = blockIdx.x * 128;

    unsigned long long acc2[4][8];
#pragma unroll
    for (int i = 0; i < 4; i++)
#pragma unroll
        for (int j = 0; j < 8; j++) acc2[i][j] = 0ull;

    for (int k0 = 0; k0 < Kr; k0 += 64) {
        // ---- load A tile (128m x 64k) transposed + swizzled ----
#pragma unroll
        for (int i = 0; i < 8; i++) {
            int e = 4 * (tid + 256 * i);
            int m = e >> 6, kk = e & 63;
            float4 v = *(const float4*)&A[(size_t)(row0 + m) * Kr + k0 + kk];
            int col = swcol128(m, (kk >> 2) & 15);
            As[(kk + 0) * 128 + col] = v.x;
            As[(kk + 1) * 128 + col] = v.y;
            As[(kk + 2) * 128 + col] = v.z;
            As[(kk + 3) * 128 + col] = v.w;
        }
        // ---- load B tile (128n x 64k) transposed + swizzled ----
#pragma unroll
        for (int i = 0; i < 8; i++) {
            int e = 4 * (tid + 256 * i);
            int n = e >> 6, kk = e & 63;
            float4 v = *(const float4*)&Bm[(size_t)(col0 + n) * Kr + k0 + kk];
            int col = swcol128(n, (kk >> 2) & 15);
            Bs[(kk + 0) * 128 + col] = v.x;
            Bs[(kk + 1) * 128 + col] = v.y;
            Bs[(kk + 2) * 128 + col] = v.z;
            Bs[(kk + 3) * 128 + col] = v.w;
        }
        __syncthreads();

#pragma unroll
        for (int k4 = 0; k4 < 16; k4++) {
            int s = k4;
#pragma unroll
            for (int j = 0; j < 4; j++) {
                int k = k4 * 4 + j;
                ulonglong2 a0 = As2[k * 32 + (tm ^ s)];        // m 4tm..+3
                ulonglong2 a1 = As2[k * 32 + 16 + (tm ^ s)];   // m 64+4tm..+3
                float4 b0 = Bs4[k * 32 + (tn ^ s)];            // n 4tn..+3
                float4 b1 = Bs4[k * 32 + 16 + (tn ^ s)];       // n 64+4tn..+3
                unsigned long long ap[4] = {a0.x, a0.y, a1.x, a1.y};
                unsigned long long bp[8] = {pk2(b0.x), pk2(b0.y), pk2(b0.z), pk2(b0.w),
                                            pk2(b1.x), pk2(b1.y), pk2(b1.z), pk2(b1.w)};
#pragma unroll
                for (int ii = 0; ii < 4; ii++)
#pragma unroll
                    for (int jj = 0; jj < 8; jj++) fma2(acc2[ii][jj], ap[ii], bp[jj]);
            }
        }
        __syncthreads();
    }

    // ---- store: pairs p -> rows; cols n = 4tn.. and 64+4tn.. ----
#pragma unroll
    for (int p = 0; p < 4; p++) {
        int mb = (p < 2) ? (4 * tm + 2 * p) : (64 + 4 * tm + 2 * (p - 2));
        float lo[8], hi[8];
#pragma unroll
        for (int j = 0; j < 8; j++) upk2(acc2[p][j], lo[j], hi[j]);
        float4 l0 = {lo[0], lo[1], lo[2], lo[3]}, l1 = {lo[4], lo[5], lo[6], lo[7]};
        float4 h0 = {hi[0], hi[1], hi[2], hi[3]}, h1 = {hi[4], hi[5], hi[6], hi[7]};
        *(float4*)&C[(size_t)(row0 + mb)     * Nr + col0 + 4 * tn]      = l0;
        *(float4*)&C[(size_t)(row0 + mb)     * Nr + col0 + 64 + 4 * tn] = l1;
        *(float4*)&C[(size_t)(row0 + mb + 1) * Nr + col0 + 4 * tn]      = h0;
        *(float4*)&C[(size_t)(row0 + mb + 1) * Nr + col0 + 64 + 4 * tn] = h1;
    }
}

// =====================================================================
// Fused segment attention, flash-style, FFMA2, 128 queries per block.
// grid: 1024 = B(2)*seg(16)*head(8)*qchunk(4); 256 threads.
// smem: Qs [d][128m] swz 32K, Ks [d][64n] swz 16K, Vs [t][64d] 16K,
//       Ps [128m][64t] 32K, m/l/fac[128] -> 99840 B -> 2 blocks/SM.
// =====================================================================
#define SMEM_ATTN ((8192 + 4096 + 4096 + 8192 + 3 * 128) * 4)
__global__ __launch_bounds__(256, 2)
void k_attn(const float* __restrict__ qkv, float* __restrict__ attn) {
    extern __shared__ float sm[];
    float* Qs   = sm;                 // 64 x 128
    float* Ks   = sm + 8192;          // 64 x 64
    float* Vs   = sm + 12288;         // 64 x 64
    float* Ps   = sm + 16384;         // 128 x 64
    float* m_sh = sm + 24576;
    float* l_sh = m_sh + 128;
    float* fac  = l_sh + 128;
    const ulonglong2* Qs2 = (const ulonglong2*)Qs;
    const float4*     Ks4 = (const float4*)Ks;
    const ulonglong2* Vs2 = (const ulonglong2*)Vs;
    const float4*     Ps4 = (const float4*)Ps;

    int tid = threadIdx.x;
    int bid = blockIdx.x;
    int qc  = bid & 3;
    int h   = (bid >> 2) & 7;
    int seg = (bid >> 5) & 15;
    int b   = bid >> 9;
    size_t base = (size_t)b * M_ * F3;
    int q0 = seg * 512 + qc * 128;

    int tq = tid >> 4;
    int tk = tid & 15;
    int warp = tid >> 5, lane = tid & 31;

    // ---- load Q tile (128q x 64d) transposed + swizzled, scaled by D^-0.5 ----
#pragma unroll
    for (int i = 0; i < 8; i++) {
        int e = 4 * (tid + 256 * i);
        int mi = e >> 6, dd = e & 63;
        int tok = g_perm[q0 + mi];
        float4 v = *(const float4*)&qkv[base + (size_t)tok * F3 + h * 64 + dd];
        int col = swcol128(mi, (dd >> 2) & 15);
        Qs[(dd + 0) * 128 + col] = 0.125f * v.x;
        Qs[(dd + 1) * 128 + col] = 0.125f * v.y;
        Qs[(dd + 2) * 128 + col] = 0.125f * v.z;
        Qs[(dd + 3) * 128 + col] = 0.125f * v.w;
    }
    if (tid < 128) { m_sh[tid] = -1e30f; l_sh[tid] = 0.f; }

    unsigned long long oacc2[8][2];   // [mi][d-pair]
#pragma unroll
    for (int i = 0; i < 8; i++) { oacc2[i][0] = 0ull; oacc2[i][1] = 0ull; }

    for (int kt = 0; kt < 8; kt++) {
        // ---- load K tile (64k x 64d) transposed + swizzled ----
#pragma unroll
        for (int i = 0; i < 4; i++) {
            int e = 4 * (tid + 256 * i);
            int nj = e >> 6, dd = e & 63;
            int tok = g_perm[seg * 512 + kt * 64 + nj];
            float4 v = *(const float4*)&qkv[base + (size_t)tok * F3 + 512 + h * 64 + dd];
            int col = (((nj >> 2) ^ ((dd >> 2) & 15)) << 2) + (nj & 3);
            Ks[(dd + 0) * 64 + col] = v.x;
            Ks[(dd + 1) * 64 + col] = v.y;
            Ks[(dd + 2) * 64 + col] = v.z;
            Ks[(dd + 3) * 64 + col] = v.w;
        }
        __syncthreads();

        // ---- S tile (128m x 64t) = Q K^T ----
        unsigned long long sacc[4][4];
#pragma unroll
        for (int p = 0; p < 4; p++)
#pragma unroll
            for (int j = 0; j < 4; j++) sacc[p][j] = 0ull;
#pragma unroll
        for (int d4 = 0; d4 < 16; d4++) {
            int s = d4;
#pragma unroll
            for (int j = 0; j < 4; j++) {
                int d = d4 * 4 + j;
                ulonglong2 qa0 = Qs2[d * 32 + (tq ^ s)];
                ulonglong2 qa1 = Qs2[d * 32 + 16 + (tq ^ s)];
                float4 kb = Ks4[d * 16 + (tk ^ s)];
                unsigned long long ap[4] = {qa0.x, qa0.y, qa1.x, qa1.y};
                unsigned long long kp[4] = {pk2(kb.x), pk2(kb.y), pk2(kb.z), pk2(kb.w)};
#pragma unroll
                for (int ii = 0; ii < 4; ii++)
#pragma unroll
                    for (int jj = 0; jj < 4; jj++) fma2(sacc[ii][jj], ap[ii], kp[jj]);
            }
        }
#pragma unroll
        for (int p = 0; p < 4; p++) {
            int mb = (p < 2) ? (4 * tq + 2 * p) : (64 + 4 * tq + 2 * (p - 2));
            float lo[4], hi[4];
#pragma unroll
            for (int j = 0; j < 4; j++) upk2(sacc[p][j], lo[j], hi[j]);
            float4 o0 = {lo[0], lo[1], lo[2], lo[3]};
            float4 o1 = {hi[0], hi[1], hi[2], hi[3]};
            *(float4*)&Ps[(mb)     * 64 + tk * 4] = o0;
            *(float4*)&Ps[(mb + 1) * 64 + tk * 4] = o1;
        }
        __syncthreads();

        // ---- online softmax update (8 warps x 16 rows) ----
        for (int r = warp; r < 128; r += 8) {
            float v0 = Ps[r * 64 + lane];
            float v1 = Ps[r * 64 + 32 + lane];
            float mx = fmaxf(v0, v1);
#pragma unroll
            for (int o = 16; o; o >>= 1) mx = fmaxf(mx, __shfl_xor_sync(0xffffffffu, mx, o));
            float mo = m_sh[r];
            float mn = fmaxf(mo, mx);
            float f  = __expf(mo - mn);
            float e0 = __expf(v0 - mn);
            float e1 = __expf(v1 - mn);
            Ps[r * 64 + lane]      = e0;
            Ps[r * 64 + 32 + lane] = e1;
            float ts = e0 + e1;
#pragma unroll
            for (int o = 16; o; o >>= 1) ts += __shfl_xor_sync(0xffffffffu, ts, o);
            if (lane == 0) { l_sh[r] = l_sh[r] * f + ts; m_sh[r] = mn; fac[r] = f; }
        }
        __syncthreads();

        // ---- rescale accumulator + load V tile ----
#pragma unroll
        for (int mi = 0; mi < 8; mi++) {
            int qrow = (mi < 4) ? (4 * tq + mi) : (64 + 4 * tq + mi - 4);
            unsigned long long fp = pk2(fac[qrow]);
            mul2(oacc2[mi][0], fp);
            mul2(oacc2[mi][1], fp);
        }

#pragma unroll
        for (int i = 0; i < 4; i++) {
            int e = 4 * (tid + 256 * i);
            int tj = e >> 6, dd = e & 63;
            int tok = g_perm[seg * 512 + kt * 64 + tj];
            float4 v = *(const float4*)&qkv[base + (size_t)tok * F3 + 1024 + h * 64 + dd];
            *(float4*)&Vs[tj * 64 + dd] = v;
        }
        __syncthreads();

        // ---- oacc += P V ----
#pragma unroll
        for (int t4 = 0; t4 < 16; t4++) {
            float4 pf[8];
#pragma unroll
            for (int mi = 0; mi < 8; mi++) {
                int qrow = (mi < 4) ? (4 * tq + mi) : (64 + 4 * tq + mi - 4);
                pf[mi] = Ps4[qrow * 16 + t4];
            }
#pragma unroll
            for (int j = 0; j < 4; j++) {
                ulonglong2 v2 = Vs2[(t4 * 4 + j) * 16 + tk];
                float pv[8];
#pragma unroll
                for (int mi = 0; mi < 8; mi++) {
                    pv[mi] = (j == 0) ? pf[mi].x : (j == 1) ? pf[mi].y : (j == 2) ? pf[mi].z : pf[mi].w;
                }
#pragma unroll
                for (int mi = 0; mi < 8; mi++) {
                    unsigned long long pp = pk2(pv[mi]);
                    fma2(oacc2[mi][0], pp, v2.x);
                    fma2(oacc2[mi][1], pp, v2.y);
                }
            }
        }
        __syncthreads();
    }

    // ---- normalize + scatter to original token order ----
#pragma unroll
    for (int mi = 0; mi < 8; mi++) {
        int qrow = (mi < 4) ? (4 * tq + mi) : (64 + 4 * tq + mi - 4);
        int tok = g_perm[q0 + qrow];
        float il = 1.f / l_sh[qrow];
        float o0, o1, o2, o3;
        upk2(oacc2[mi][0], o0, o1);
        upk2(oacc2[mi][1], o2, o3);
        float4 o = {o0 * il, o1 * il, o2 * il, o3 * il};
        *(float4*)&attn[((size_t)b * M_ + tok) * HD + h * 64 + tk * 4] = o;
    }
}

// ---------------- launch ----------------
extern "C" void kernel_launch(void* const* d_in, const int* in_sizes, int n_in,
                              void* d_out, int out_size) {
    const float* q     = (const float*)d_in[0];
    const float* w_qkv = (const float*)d_in[3];
    const float* w_out = (const float*)d_in[4];
    float* out = (float*)d_out;

    void *p_x, *p_weff, *p_qkv, *p_attn;
    cudaGetSymbolAddress(&p_x,    g_x);
    cudaGetSymbolAddress(&p_weff, g_weff);
    cudaGetSymbolAddress(&p_qkv,  g_qkv);
    cudaGetSymbolAddress(&p_attn, g_attn);

    cudaFuncSetAttribute(k_attn, cudaFuncAttributeMaxDynamicSharedMemorySize, SMEM_ATTN);
    cudaFuncSetAttribute(k_gemm_nt, cudaFuncAttributeMaxDynamicSharedMemorySize, 65536);

    k_zero_flags<<<64, 256>>>();
    k_hilbert<<<32, 256>>>();
    k_scan<<<1, 256>>>();
    k_rank<<<32, 256>>>();

    k_weff<<<(F3 * D_ + 255) / 256, 256>>>(w_qkv);
    k_mean<<<(B_ * M_ * D_ + 255) / 256, 256>>>(q);

    // GEMM1: qkv[16384,1536] = x[16384,64] * weff[1536,64]^T
    {
        dim3 grd(F3 / 128, (B_ * M_) / 128);
        k_gemm_nt<<<grd, 256, 65536>>>((const float*)p_x, (const float*)p_weff,
                                       (float*)p_qkv, B_ * M_, F3, D_);
    }

    // fused segment attention
    k_attn<<<B_ * NSEG * H_ * 4, 256, SMEM_ATTN>>>((const float*)p_qkv, (float*)p_attn);

    // GEMM2: out[16384,512] = attn[16384,512] * w_out[512,512]^T
    {
        dim3 grd(HD / 128, (B_ * M_) / 128);
        k_gemm_nt<<<grd, 256, 65536>>>((const float*)p_attn, w_out, out, B_ * M_, HD, HD);
    }
}

// round 10
// speedup vs baseline: 2.9007x; 1.1289x over previous
#include <cuda_runtime.h>
#include <cuda_bf16.h>
#include <math.h>
#include <stdint.h>

// Problem constants
#define B_   2
#define M_   8192
#define H_   8
#define D_   64
#define HD   512
#define F3   1536
#define NSEG 16

// ---------------- f32x2 packed helpers (FFMA2 path, attention) ----------------
__device__ __forceinline__ unsigned long long pk2(float v) {
    unsigned long long r;
    asm("mov.b64 %0, {%1, %1};" : "=l"(r) : "f"(v));
    return r;
}
__device__ __forceinline__ void fma2(unsigned long long& c, unsigned long long a, unsigned long long b) {
    asm("fma.rn.f32x2 %0, %1, %2, %0;" : "+l"(c) : "l"(a), "l"(b));
}
__device__ __forceinline__ void mul2(unsigned long long& d, unsigned long long a) {
    asm("mul.rn.f32x2 %0, %1, %0;" : "+l"(d) : "l"(a));
}
__device__ __forceinline__ void upk2(unsigned long long v, float& lo, float& hi) {
    asm("mov.b64 {%0, %1}, %2;" : "=f"(lo), "=f"(hi) : "l"(v));
}

// swizzled column for a 128-element row (half-split slot layout)
__device__ __forceinline__ int swcol128(int e, int s) {
    int g = e >> 2;
    int c4 = (g & 16) | ((g & 15) ^ s);
    return c4 * 4 + (e & 3);
}

// ---------------- bf16 helpers ----------------
__device__ __forceinline__ uint32_t pkbf(float a, float b) {
    __nv_bfloat162 t = __floats2bfloat162_rn(a, b);
    return *reinterpret_cast<uint32_t*>(&t);
}
__device__ __forceinline__ float tobf(float a) {
    return __bfloat162float(__float2bfloat16_rn(a));
}
// SW128 byte swizzle (Swizzle<3,4,3>)
#define SWZ(o) ((o) ^ (((o) >> 3) & 0x70))

// mma.sync m16n8k16 bf16 (arch-portable tensor path; valid on compute_103)
__device__ __forceinline__ void mma16816(float* c, const uint32_t* a, const uint32_t* b) {
    asm volatile(
        "mma.sync.aligned.m16n8k16.row.col.f32.bf16.bf16.f32 "
        "{%0,%1,%2,%3}, {%4,%5,%6,%7}, {%8,%9}, {%0,%1,%2,%3};"
        : "+f"(c[0]), "+f"(c[1]), "+f"(c[2]), "+f"(c[3])
        : "r"(a[0]), "r"(a[1]), "r"(a[2]), "r"(a[3]), "r"(b[0]), "r"(b[1]));
}

// ---------------- device scratch ----------------
__device__ int      g_perm[M_];
__device__ int      g_dval[M_];
__device__ unsigned g_flags[16384];
__device__ unsigned g_psum[16384];
__device__ float    g_x[B_ * M_ * D_];
__device__ float    g_weff[F3 * D_];
__device__ float    g_qkv[(size_t)B_ * M_ * F3];
__device__ float    g_attn[(size_t)B_ * M_ * HD];

// ---------------- Hilbert permutation ----------------
__global__ void k_zero_flags() {
    int i = blockIdx.x * 256 + threadIdx.x;
    if (i < 16384) g_flags[i] = 0u;
}

__global__ void k_hilbert() {
    int i = blockIdx.x * 256 + threadIdx.x;
    if (i >= M_) return;
    int x = i & 127, y = i >> 7;
    int d = 0;
    for (int s = 64; s > 0; s >>= 1) {
        int rx = (x & s) ? 1 : 0;
        int ry = (y & s) ? 1 : 0;
        d += s * s * ((3 * rx) ^ ry);
        if (ry == 0) {
            if (rx == 1) { x = s - 1 - x; y = s - 1 - y; }
            int t = x; x = y; y = t;
        }
    }
    g_dval[i] = d;
    g_flags[d] = 1u;
}

__global__ void k_scan() {
    __shared__ unsigned part[256];
    int t = threadIdx.x;
    unsigned s = 0;
    for (int i = 0; i < 64; i++) s += g_flags[t * 64 + i];
    part[t] = s;
    __syncthreads();
    if (t == 0) {
        unsigned run = 0;
        for (int i = 0; i < 256; i++) { unsigned v = part[i]; part[i] = run; run += v; }
    }
    __syncthreads();
    unsigned run = part[t];
    for (int i = 0; i < 64; i++) {
        unsigned v = g_flags[t * 64 + i];
        g_psum[t * 64 + i] = run;
        run += v;
    }
}

__global__ void k_rank() {
    int i = blockIdx.x * 256 + threadIdx.x;
    if (i >= M_) return;
    g_perm[g_psum[g_dval[i]]] = i;
}

// ---------------- head-reduced weight + head-sum of q ----------------
__global__ void k_weff(const float* __restrict__ w_qkv) {
    int e = blockIdx.x * 256 + threadIdx.x;
    if (e >= F3 * D_) return;
    int f = e >> 6, d = e & 63;
    float s = 0.f;
#pragma unroll
    for (int h = 0; h < 8; h++) s += w_qkv[f * HD + h * 64 + d];
    g_weff[e] = 0.125f * s;
}

__global__ void k_mean(const float* __restrict__ q) {
    int e = blockIdx.x * 256 + threadIdx.x;
    if (e >= B_ * M_ * D_) return;
    int row = e >> 6, d = e & 63;
    const float* p = q + (size_t)row * HD + d;
    float s = 0.f;
#pragma unroll
    for (int h = 0; h < 8; h++) s += p[h * 64];
    g_x[e] = s;
}

// =====================================================================
// Tensor-core GEMM via mma.sync bf16 x3 split:
//   C[Mr,Nr] = A[Mr,Kr] * B[Nr,Kr]^T,  D = aH*bH + aH*bL + aL*bH (fp32 acc)
// 128x128 tile per CTA, 256 threads = 8 warps (2m x 4n), warp tile 64x32.
// Smem: bf16 tiles AH/AL/BH/BL, 128 rows x 64 k, 128B rows, SW128 swizzle.
// =====================================================================
#define GM_SMEM 65536
__global__ __launch_bounds__(256)
void k_gemm_mma(const float* __restrict__ A, const float* __restrict__ Bm,
                float* __restrict__ C, int Nr, int Kr) {
    extern __shared__ __align__(1024) char smc[];
    const int SM_AH = 0, SM_AL = 16384, SM_BH = 32768, SM_BL = 49152;

    int tid = threadIdx.x;
    int wid = tid >> 5, lane = tid & 31;
    int g = lane >> 2, t4 = lane & 3;
    int gx = g << 4;                       // per-lane swizzle XOR (rows are 128B)
    int warp_m = (wid >> 2) * 64;          // 0 or 64
    int warp_n = (wid & 3) * 32;           // 0,32,64,96
    int row0 = blockIdx.y * 128, col0 = blockIdx.x * 128;

    float acc[4][4][4];                    // [mt][nt][frag]
#pragma unroll
    for (int i = 0; i < 4; i++)
#pragma unroll
        for (int j = 0; j < 4; j++)
#pragma unroll
            for (int r = 0; r < 4; r++) acc[i][j][r] = 0.f;

    int nch = Kr >> 6;
    for (int c = 0; c < nch; c++) {
        // ---- fill: load fp32 chunk, split to bf16 hi/lo, store swizzled ----
#pragma unroll
        for (int i = 0; i < 8; i++) {
            int e = 4 * (tid + 256 * i);
            int r = e >> 6, kk = e & 63;
            float4 v = *(const float4*)&A[(size_t)(row0 + r) * Kr + c * 64 + kk];
            float h0 = tobf(v.x), h1 = tobf(v.y), h2 = tobf(v.z), h3 = tobf(v.w);
            uint32_t so = SWZ((uint32_t)(r * 128 + kk * 2));
            *(uint32_t*)(smc + SM_AH + so)     = pkbf(h0, h1);
            *(uint32_t*)(smc + SM_AH + so + 4) = pkbf(h2, h3);
            *(uint32_t*)(smc + SM_AL + so)     = pkbf(v.x - h0, v.y - h1);
            *(uint32_t*)(smc + SM_AL + so + 4) = pkbf(v.z - h2, v.w - h3);
        }
#pragma unroll
        for (int i = 0; i < 8; i++) {
            int e = 4 * (tid + 256 * i);
            int r = e >> 6, kk = e & 63;
            float4 v = *(const float4*)&Bm[(size_t)(col0 + r) * Kr + c * 64 + kk];
            float h0 = tobf(v.x), h1 = tobf(v.y), h2 = tobf(v.z), h3 = tobf(v.w);
            uint32_t so = SWZ((uint32_t)(r * 128 + kk * 2));
            *(uint32_t*)(smc + SM_BH + so)     = pkbf(h0, h1);
            *(uint32_t*)(smc + SM_BH + so + 4) = pkbf(h2, h3);
            *(uint32_t*)(smc + SM_BL + so)     = pkbf(v.x - h0, v.y - h1);
            *(uint32_t*)(smc + SM_BL + so + 4) = pkbf(v.z - h2, v.w - h3);
        }
        __syncthreads();

        // ---- compute: 4 k16 steps x 3 split passes ----
#pragma unroll
        for (int kq = 0; kq < 4; kq++) {
            uint32_t aH[4][4], bH[4][2], bL[4][2], aL[4][4];
            // A hi fragments: rows g/g+8, kbytes kq*32 + 4t4 (+16)
#pragma unroll
            for (int mt = 0; mt < 4; mt++) {
                int rb = (warp_m + mt * 16 + g) * 128;
                int l0 = (kq * 32 + t4 * 4) ^ gx;
                int l1 = (kq * 32 + t4 * 4 + 16) ^ gx;
                aH[mt][0] = *(const uint32_t*)(smc + SM_AH + rb + l0);
                aH[mt][1] = *(const uint32_t*)(smc + SM_AH + rb + 1024 + l0);
                aH[mt][2] = *(const uint32_t*)(smc + SM_AH + rb + l1);
                aH[mt][3] = *(const uint32_t*)(smc + SM_AH + rb + 1024 + l1);
            }
#pragma unroll
            for (int nt = 0; nt < 4; nt++) {
                int rb = (warp_n + nt * 8 + g) * 128;
                int l0 = (kq * 32 + t4 * 4) ^ gx;
                int l1 = (kq * 32 + t4 * 4 + 16) ^ gx;
                bH[nt][0] = *(const uint32_t*)(smc + SM_BH + rb + l0);
                bH[nt][1] = *(const uint32_t*)(smc + SM_BH + rb + l1);
            }
#pragma unroll
            for (int mt = 0; mt < 4; mt++)
#pragma unroll
                for (int nt = 0; nt < 4; nt++) mma16816(acc[mt][nt], aH[mt], bH[nt]);

#pragma unroll
            for (int nt = 0; nt < 4; nt++) {
                int rb = (warp_n + nt * 8 + g) * 128;
                int l0 = (kq * 32 + t4 * 4) ^ gx;
                int l1 = (kq * 32 + t4 * 4 + 16) ^ gx;
                bL[nt][0] = *(const uint32_t*)(smc + SM_BL + rb + l0);
                bL[nt][1] = *(const uint32_t*)(smc + SM_BL + rb + l1);
            }
#pragma unroll
            for (int mt = 0; mt < 4; mt++)
#pragma unroll
                for (int nt = 0; nt < 4; nt++) mma16816(acc[mt][nt], aH[mt], bL[nt]);

#pragma unroll
            for (int mt = 0; mt < 4; mt++) {
                int rb = (warp_m + mt * 16 + g) * 128;
                int l0 = (kq * 32 + t4 * 4) ^ gx;
                int l1 = (kq * 32 + t4 * 4 + 16) ^ gx;
                aL[mt][0] = *(const uint32_t*)(smc + SM_AL + rb + l0);
                aL[mt][1] = *(const uint32_t*)(smc + SM_AL + rb + 1024 + l0);
                aL[mt][2] = *(const uint32_t*)(smc + SM_AL + rb + l1);
                aL[mt][3] = *(const uint32_t*)(smc + SM_AL + rb + 1024 + l1);
            }
#pragma unroll
            for (int mt = 0; mt < 4; mt++)
#pragma unroll
                for (int nt = 0; nt < 4; nt++) mma16816(acc[mt][nt], aL[mt], bH[nt]);
        }
        __syncthreads();
    }

    // ---- epilogue: per-fragment STG.64 (32B sector-aligned groups) ----
#pragma unroll
    for (int mt = 0; mt < 4; mt++) {
        int mrow = row0 + warp_m + mt * 16 + g;
#pragma unroll
        for (int nt = 0; nt < 4; nt++) {
            int ncol = col0 + warp_n + nt * 8 + 2 * t4;
            float2 lo = {acc[mt][nt][0], acc[mt][nt][1]};
            float2 hi = {acc[mt][nt][2], acc[mt][nt][3]};
            *(float2*)&C[(size_t)mrow * Nr + ncol]       = lo;
            *(float2*)&C[(size_t)(mrow + 8) * Nr + ncol] = hi;
        }
    }
}

// =====================================================================
// Fused segment attention (R6, unchanged): FFMA2, 128 queries per block.
// =====================================================================
#define SMEM_ATTN ((8192 + 4096 + 4096 + 8192 + 3 * 128) * 4)
__global__ __launch_bounds__(256, 2)
void k_attn(const float* __restrict__ qkv, float* __restrict__ attn) {
    extern __shared__ float sm[];
    float* Qs   = sm;
    float* Ks   = sm + 8192;
    float* Vs   = sm + 12288;
    float* Ps   = sm + 16384;
    float* m_sh = sm + 24576;
    float* l_sh = m_sh + 128;
    float* fac  = l_sh + 128;
    const ulonglong2* Qs2 = (const ulonglong2*)Qs;
    const float4*     Ks4 = (const float4*)Ks;
    const ulonglong2* Vs2 = (const ulonglong2*)Vs;
    const float4*     Ps4 = (const float4*)Ps;

    int tid = threadIdx.x;
    int bid = blockIdx.x;
    int qc  = bid & 3;
    int h   = (bid >> 2) & 7;
    int seg = (bid >> 5) & 15;
    int b   = bid >> 9;
    size_t base = (size_t)b * M_ * F3;
    int q0 = seg * 512 + qc * 128;

    int tq = tid >> 4;
    int tk = tid & 15;
    int warp = tid >> 5, lane = tid & 31;

#pragma unroll
    for (int i = 0; i < 8; i++) {
        int e = 4 * (tid + 256 * i);
        int mi = e >> 6, dd = e & 63;
        int tok = g_perm[q0 + mi];
        float4 v = *(const float4*)&qkv[base + (size_t)tok * F3 + h * 64 + dd];
        int col = swcol128(mi, (dd >> 2) & 15);
        Qs[(dd + 0) * 128 + col] = 0.125f * v.x;
        Qs[(dd + 1) * 128 + col] = 0.125f * v.y;
        Qs[(dd + 2) * 128 + col] = 0.125f * v.z;
        Qs[(dd + 3) * 128 + col] = 0.125f * v.w;
    }
    if (tid < 128) { m_sh[tid] = -1e30f; l_sh[tid] = 0.f; }

    unsigned long long oacc2[8][2];
#pragma unroll
    for (int i = 0; i < 8; i++) { oacc2[i][0] = 0ull; oacc2[i][1] = 0ull; }

    for (int kt = 0; kt < 8; kt++) {
#pragma unroll
        for (int i = 0; i < 4; i++) {
            int e = 4 * (tid + 256 * i);
            int nj = e >> 6, dd = e & 63;
            int tok = g_perm[seg * 512 + kt * 64 + nj];
            float4 v = *(const float4*)&qkv[base + (size_t)tok * F3 + 512 + h * 64 + dd];
            int col = (((nj >> 2) ^ ((dd >> 2) & 15)) << 2) + (nj & 3);
            Ks[(dd + 0) * 64 + col] = v.x;
            Ks[(dd + 1) * 64 + col] = v.y;
            Ks[(dd + 2) * 64 + col] = v.z;
            Ks[(dd + 3) * 64 + col] = v.w;
        }
        __syncthreads();

        unsigned long long sacc[4][4];
#pragma unroll
        for (int p = 0; p < 4; p++)
#pragma unroll
            for (int j = 0; j < 4; j++) sacc[p][j] = 0ull;
#pragma unroll
        for (int d4 = 0; d4 < 16; d4++) {
            int s = d4;
#pragma unroll
            for (int j = 0; j < 4; j++) {
                int d = d4 * 4 + j;
                ulonglong2 qa0 = Qs2[d * 32 + (tq ^ s)];
                ulonglong2 qa1 = Qs2[d * 32 + 16 + (tq ^ s)];
                float4 kb = Ks4[d * 16 + (tk ^ s)];
                unsigned long long ap[4] = {qa0.x, qa0.y, qa1.x, qa1.y};
                unsigned long long kp[4] = {pk2(kb.x), pk2(kb.y), pk2(kb.z), pk2(kb.w)};
#pragma unroll
                for (int ii = 0; ii < 4; ii++)
#pragma unroll
                    for (int jj = 0; jj < 4; jj++) fma2(sacc[ii][jj], ap[ii], kp[jj]);
            }
        }
#pragma unroll
        for (int p = 0; p < 4; p++) {
            int mb = (p < 2) ? (4 * tq + 2 * p) : (64 + 4 * tq + 2 * (p - 2));
            float lo[4], hi[4];
#pragma unroll
            for (int j = 0; j < 4; j++) upk2(sacc[p][j], lo[j], hi[j]);
            float4 o0 = {lo[0], lo[1], lo[2], lo[3]};
            float4 o1 = {hi[0], hi[1], hi[2], hi[3]};
            *(float4*)&Ps[(mb)     * 64 + tk * 4] = o0;
            *(float4*)&Ps[(mb + 1) * 64 + tk * 4] = o1;
        }
        __syncthreads();

        for (int r = warp; r < 128; r += 8) {
            float v0 = Ps[r * 64 + lane];
            float v1 = Ps[r * 64 + 32 + lane];
            float mx = fmaxf(v0, v1);
#pragma unroll
            for (int o = 16; o; o >>= 1) mx = fmaxf(mx, __shfl_xor_sync(0xffffffffu, mx, o));
            float mo = m_sh[r];
            float mn = fmaxf(mo, mx);
            float f  = __expf(mo - mn);
            float e0 = __expf(v0 - mn);
            float e1 = __expf(v1 - mn);
            Ps[r * 64 + lane]      = e0;
            Ps[r * 64 + 32 + lane] = e1;
            float ts = e0 + e1;
#pragma unroll
            for (int o = 16; o; o >>= 1) ts += __shfl_xor_sync(0xffffffffu, ts, o);
            if (lane == 0) { l_sh[r] = l_sh[r] * f + ts; m_sh[r] = mn; fac[r] = f; }
        }
        __syncthreads();

#pragma unroll
        for (int mi = 0; mi < 8; mi++) {
            int qrow = (mi < 4) ? (4 * tq + mi) : (64 + 4 * tq + mi - 4);
            unsigned long long fp = pk2(fac[qrow]);
            mul2(oacc2[mi][0], fp);
            mul2(oacc2[mi][1], fp);
        }

#pragma unroll
        for (int i = 0; i < 4; i++) {
            int e = 4 * (tid + 256 * i);
            int tj = e >> 6, dd = e & 63;
            int tok = g_perm[seg * 512 + kt * 64 + tj];
            float4 v = *(const float4*)&qkv[base + (size_t)tok * F3 + 1024 + h * 64 + dd];
            *(float4*)&Vs[tj * 64 + dd] = v;
        }
        __syncthreads();

#pragma unroll
        for (int t4i = 0; t4i < 16; t4i++) {
            float4 pf[8];
#pragma unroll
            for (int mi = 0; mi < 8; mi++) {
                int qrow = (mi < 4) ? (4 * tq + mi) : (64 + 4 * tq + mi - 4);
                pf[mi] = Ps4[qrow * 16 + t4i];
            }
#pragma unroll
            for (int j = 0; j < 4; j++) {
                ulonglong2 v2 = Vs2[(t4i * 4 + j) * 16 + tk];
                float pv[8];
#pragma unroll
                for (int mi = 0; mi < 8; mi++) {
                    pv[mi] = (j == 0) ? pf[mi].x : (j == 1) ? pf[mi].y : (j == 2) ? pf[mi].z : pf[mi].w;
                }
#pragma unroll
                for (int mi = 0; mi < 8; mi++) {
                    unsigned long long pp = pk2(pv[mi]);
                    fma2(oacc2[mi][0], pp, v2.x);
                    fma2(oacc2[mi][1], pp, v2.y);
                }
            }
        }
        __syncthreads();
    }

#pragma unroll
    for (int mi = 0; mi < 8; mi++) {
        int qrow = (mi < 4) ? (4 * tq + mi) : (64 + 4 * tq + mi - 4);
        int tok = g_perm[q0 + qrow];
        float il = 1.f / l_sh[qrow];
        float o0, o1, o2, o3;
        upk2(oacc2[mi][0], o0, o1);
        upk2(oacc2[mi][1], o2, o3);
        float4 o = {o0 * il, o1 * il, o2 * il, o3 * il};
        *(float4*)&attn[((size_t)b * M_ + tok) * HD + h * 64 + tk * 4] = o;
    }
}

// ---------------- launch ----------------
extern "C" void kernel_launch(void* const* d_in, const int* in_sizes, int n_in,
                              void* d_out, int out_size) {
    const float* q     = (const float*)d_in[0];
    const float* w_qkv = (const float*)d_in[3];
    const float* w_out = (const float*)d_in[4];
    float* out = (float*)d_out;

    void *p_x, *p_weff, *p_qkv, *p_attn;
    cudaGetSymbolAddress(&p_x,    g_x);
    cudaGetSymbolAddress(&p_weff, g_weff);
    cudaGetSymbolAddress(&p_qkv,  g_qkv);
    cudaGetSymbolAddress(&p_attn, g_attn);

    cudaFuncSetAttribute(k_attn, cudaFuncAttributeMaxDynamicSharedMemorySize, SMEM_ATTN);
    cudaFuncSetAttribute(k_gemm_mma, cudaFuncAttributeMaxDynamicSharedMemorySize, GM_SMEM);

    k_zero_flags<<<64, 256>>>();
    k_hilbert<<<32, 256>>>();
    k_scan<<<1, 256>>>();
    k_rank<<<32, 256>>>();

    k_weff<<<(F3 * D_ + 255) / 256, 256>>>(w_qkv);
    k_mean<<<(B_ * M_ * D_ + 255) / 256, 256>>>(q);

    // GEMM1: qkv[16384,1536] = x[16384,64] * weff[1536,64]^T  (mma.sync bf16x3)
    {
        dim3 grd(F3 / 128, (B_ * M_) / 128);
        k_gemm_mma<<<grd, 256, GM_SMEM>>>((const float*)p_x, (const float*)p_weff,
                                          (float*)p_qkv, F3, D_);
    }

    // fused segment attention (SIMT FFMA2)
    k_attn<<<B_ * NSEG * H_ * 4, 256, SMEM_ATTN>>>((const float*)p_qkv, (float*)p_attn);

    // GEMM2: out[16384,512] = attn[16384,512] * w_out[512,512]^T  (mma.sync bf16x3)
    {
        dim3 grd(HD / 128, (B_ * M_) / 128);
        k_gemm_mma<<<grd, 256, GM_SMEM>>>((const float*)p_attn, w_out, out, HD, HD);
    }
}

// round 12
// speedup vs baseline: 4.4724x; 1.5418x over previous
#include <cuda_runtime.h>
#include <cuda_bf16.h>
#include <math.h>
#include <stdint.h>

// Problem constants
#define B_   2
#define M_   8192
#define H_   8
#define D_   64
#define HD   512
#define F3   1536
#define NSEG 16

// ---------------- bf16 helpers ----------------
__device__ __forceinline__ uint32_t pkbf(float a, float b) {
    __nv_bfloat162 t = __floats2bfloat162_rn(a, b);
    return *reinterpret_cast<uint32_t*>(&t);
}
__device__ __forceinline__ float tobf(float a) {
    return __bfloat162float(__float2bfloat16_rn(a));
}
// SW128 byte swizzle (Swizzle<3,4,3>)
#define SWZ(o) ((o) ^ (((o) >> 3) & 0x70))

// mma.sync m16n8k16 bf16 (arch-portable tensor path)
__device__ __forceinline__ void mma16816(float* c, const uint32_t* a, const uint32_t* b) {
    asm volatile(
        "mma.sync.aligned.m16n8k16.row.col.f32.bf16.bf16.f32 "
        "{%0,%1,%2,%3}, {%4,%5,%6,%7}, {%8,%9}, {%0,%1,%2,%3};"
        : "+f"(c[0]), "+f"(c[1]), "+f"(c[2]), "+f"(c[3])
        : "r"(a[0]), "r"(a[1]), "r"(a[2]), "r"(a[3]), "r"(b[0]), "r"(b[1]));
}

// ---------------- device scratch ----------------
__device__ int      g_perm[M_];
__device__ int      g_dval[M_];
__device__ unsigned g_flags[16384];
__device__ unsigned g_psum[16384];
__device__ float    g_x[B_ * M_ * D_];
__device__ float    g_weff[F3 * D_];
__device__ float    g_qkv[(size_t)B_ * M_ * F3];
__device__ float    g_attn[(size_t)B_ * M_ * HD];

// ---------------- Hilbert permutation ----------------
__global__ void k_zero_flags() {
    int i = blockIdx.x * 256 + threadIdx.x;
    if (i < 16384) g_flags[i] = 0u;
}

__global__ void k_hilbert() {
    int i = blockIdx.x * 256 + threadIdx.x;
    if (i >= M_) return;
    int x = i & 127, y = i >> 7;
    int d = 0;
    for (int s = 64; s > 0; s >>= 1) {
        int rx = (x & s) ? 1 : 0;
        int ry = (y & s) ? 1 : 0;
        d += s * s * ((3 * rx) ^ ry);
        if (ry == 0) {
            if (rx == 1) { x = s - 1 - x; y = s - 1 - y; }
            int t = x; x = y; y = t;
        }
    }
    g_dval[i] = d;
    g_flags[d] = 1u;
}

__global__ void k_scan() {
    __shared__ unsigned part[256];
    int t = threadIdx.x;
    unsigned s = 0;
    for (int i = 0; i < 64; i++) s += g_flags[t * 64 + i];
    part[t] = s;
    __syncthreads();
    if (t == 0) {
        unsigned run = 0;
        for (int i = 0; i < 256; i++) { unsigned v = part[i]; part[i] = run; run += v; }
    }
    __syncthreads();
    unsigned run = part[t];
    for (int i = 0; i < 64; i++) {
        unsigned v = g_flags[t * 64 + i];
        g_psum[t * 64 + i] = run;
        run += v;
    }
}

__global__ void k_rank() {
    int i = blockIdx.x * 256 + threadIdx.x;
    if (i >= M_) return;
    g_perm[g_psum[g_dval[i]]] = i;
}

// ---------------- head-reduced weight + head-sum of q ----------------
__global__ void k_weff(const float* __restrict__ w_qkv) {
    int e = blockIdx.x * 256 + threadIdx.x;
    if (e >= F3 * D_) return;
    int f = e >> 6, d = e & 63;
    float s = 0.f;
#pragma unroll
    for (int h = 0; h < 8; h++) s += w_qkv[f * HD + h * 64 + d];
    g_weff[e] = 0.125f * s;
}

__global__ void k_mean(const float* __restrict__ q) {
    int e = blockIdx.x * 256 + threadIdx.x;
    if (e >= B_ * M_ * D_) return;
    int row = e >> 6, d = e & 63;
    const float* p = q + (size_t)row * HD + d;
    float s = 0.f;
#pragma unroll
    for (int h = 0; h < 8; h++) s += p[h * 64];
    g_x[e] = s;
}

// =====================================================================
// Tensor-core GEMM via mma.sync bf16 x3 split (R10, proven).
// =====================================================================
#define GM_SMEM 65536
__global__ __launch_bounds__(256)
void k_gemm_mma(const float* __restrict__ A, const float* __restrict__ Bm,
                float* __restrict__ C, int Nr, int Kr) {
    extern __shared__ __align__(1024) char smc[];
    const int SM_AH = 0, SM_AL = 16384, SM_BH = 32768, SM_BL = 49152;

    int tid = threadIdx.x;
    int wid = tid >> 5, lane = tid & 31;
    int g = lane >> 2, t4 = lane & 3;
    int gx = g << 4;
    int warp_m = (wid >> 2) * 64;
    int warp_n = (wid & 3) * 32;
    int row0 = blockIdx.y * 128, col0 = blockIdx.x * 128;

    float acc[4][4][4];
#pragma unroll
    for (int i = 0; i < 4; i++)
#pragma unroll
        for (int j = 0; j < 4; j++)
#pragma unroll
            for (int r = 0; r < 4; r++) acc[i][j][r] = 0.f;

    int nch = Kr >> 6;
    for (int c = 0; c < nch; c++) {
#pragma unroll
        for (int i = 0; i < 8; i++) {
            int e = 4 * (tid + 256 * i);
            int r = e >> 6, kk = e & 63;
            float4 v = *(const float4*)&A[(size_t)(row0 + r) * Kr + c * 64 + kk];
            float h0 = tobf(v.x), h1 = tobf(v.y), h2 = tobf(v.z), h3 = tobf(v.w);
            uint32_t so = SWZ((uint32_t)(r * 128 + kk * 2));
            *(uint32_t*)(smc + SM_AH + so)     = pkbf(h0, h1);
            *(uint32_t*)(smc + SM_AH + so + 4) = pkbf(h2, h3);
            *(uint32_t*)(smc + SM_AL + so)     = pkbf(v.x - h0, v.y - h1);
            *(uint32_t*)(smc + SM_AL + so + 4) = pkbf(v.z - h2, v.w - h3);
        }
#pragma unroll
        for (int i = 0; i < 8; i++) {
            int e = 4 * (tid + 256 * i);
            int r = e >> 6, kk = e & 63;
            float4 v = *(const float4*)&Bm[(size_t)(col0 + r) * Kr + c * 64 + kk];
            float h0 = tobf(v.x), h1 = tobf(v.y), h2 = tobf(v.z), h3 = tobf(v.w);
            uint32_t so = SWZ((uint32_t)(r * 128 + kk * 2));
            *(uint32_t*)(smc + SM_BH + so)     = pkbf(h0, h1);
            *(uint32_t*)(smc + SM_BH + so + 4) = pkbf(h2, h3);
            *(uint32_t*)(smc + SM_BL + so)     = pkbf(v.x - h0, v.y - h1);
            *(uint32_t*)(smc + SM_BL + so + 4) = pkbf(v.z - h2, v.w - h3);
        }
        __syncthreads();

#pragma unroll
        for (int kq = 0; kq < 4; kq++) {
            uint32_t aH[4][4], bH[4][2], bL[4][2], aL[4][4];
            int l0 = (kq * 32 + t4 * 4) ^ gx;
            int l1 = (kq * 32 + t4 * 4 + 16) ^ gx;
#pragma unroll
            for (int mt = 0; mt < 4; mt++) {
                int rb = (warp_m + mt * 16 + g) * 128;
                aH[mt][0] = *(const uint32_t*)(smc + SM_AH + rb + l0);
                aH[mt][1] = *(const uint32_t*)(smc + SM_AH + rb + 1024 + l0);
                aH[mt][2] = *(const uint32_t*)(smc + SM_AH + rb + l1);
                aH[mt][3] = *(const uint32_t*)(smc + SM_AH + rb + 1024 + l1);
            }
#pragma unroll
            for (int nt = 0; nt < 4; nt++) {
                int rb = (warp_n + nt * 8 + g) * 128;
                bH[nt][0] = *(const uint32_t*)(smc + SM_BH + rb + l0);
                bH[nt][1] = *(const uint32_t*)(smc + SM_BH + rb + l1);
            }
#pragma unroll
            for (int mt = 0; mt < 4; mt++)
#pragma unroll
                for (int nt = 0; nt < 4; nt++) mma16816(acc[mt][nt], aH[mt], bH[nt]);

#pragma unroll
            for (int nt = 0; nt < 4; nt++) {
                int rb = (warp_n + nt * 8 + g) * 128;
                bL[nt][0] = *(const uint32_t*)(smc + SM_BL + rb + l0);
                bL[nt][1] = *(const uint32_t*)(smc + SM_BL + rb + l1);
            }
#pragma unroll
            for (int mt = 0; mt < 4; mt++)
#pragma unroll
                for (int nt = 0; nt < 4; nt++) mma16816(acc[mt][nt], aH[mt], bL[nt]);

#pragma unroll
            for (int mt = 0; mt < 4; mt++) {
                int rb = (warp_m + mt * 16 + g) * 128;
                aL[mt][0] = *(const uint32_t*)(smc + SM_AL + rb + l0);
                aL[mt][1] = *(const uint32_t*)(smc + SM_AL + rb + 1024 + l0);
                aL[mt][2] = *(const uint32_t*)(smc + SM_AL + rb + l1);
                aL[mt][3] = *(const uint32_t*)(smc + SM_AL + rb + 1024 + l1);
            }
#pragma unroll
            for (int mt = 0; mt < 4; mt++)
#pragma unroll
                for (int nt = 0; nt < 4; nt++) mma16816(acc[mt][nt], aL[mt], bH[nt]);
        }
        __syncthreads();
    }

#pragma unroll
    for (int mt = 0; mt < 4; mt++) {
        int mrow = row0 + warp_m + mt * 16 + g;
#pragma unroll
        for (int nt = 0; nt < 4; nt++) {
            int ncol = col0 + warp_n + nt * 8 + 2 * t4;
            float2 lo = {acc[mt][nt][0], acc[mt][nt][1]};
            float2 hi = {acc[mt][nt][2], acc[mt][nt][3]};
            *(float2*)&C[(size_t)mrow * Nr + ncol]       = lo;
            *(float2*)&C[(size_t)(mrow + 8) * Nr + ncol] = hi;
        }
    }
}

// =====================================================================
// Fused segment attention on mma.sync bf16x3, flash softmax in registers.
// grid: 1024 = B(2)*seg(16)*head(8)*qchunk(4); 256 threads = 8 warps.
// Warp tile: 16 queries x 64 keys (QK) / 16 queries x 64 d (PV).
// P never touches smem: QK accumulator fragments are re-split in
// registers into the PV A-operand fragments.
// smem: QH/QL 128x64 bf16 (32K, persistent), KH/KL 64x64 (16K/tile),
//       VH/VL [d][t] 64x64 (16K/tile) = 64KB total -> 2 blocks/SM.
// =====================================================================
#define ATT_SMEM 65536
__global__ __launch_bounds__(256, 2)
void k_attn(const float* __restrict__ qkv, float* __restrict__ attn) {
    extern __shared__ __align__(1024) char smc[];
    const int SM_QH = 0, SM_QL = 16384;
    const int SM_KH = 32768, SM_KL = 40960;
    const int SM_VH = 49152, SM_VL = 57344;

    int tid = threadIdx.x;
    int wid = tid >> 5, lane = tid & 31;
    int g = lane >> 2, t4 = lane & 3;
    int gx = g << 4;
    int warp_m = wid * 16;

    int bid = blockIdx.x;
    int qc  = bid & 3;
    int h   = (bid >> 2) & 7;
    int seg = (bid >> 5) & 15;
    int b   = bid >> 9;
    size_t base = (size_t)b * M_ * F3;
    int q0 = seg * 512 + qc * 128;

    // ---- stage Q (128q x 64d), scaled by 0.125, bf16 hi/lo, SW128 ----
#pragma unroll
    for (int i = 0; i < 8; i++) {
        int e = 4 * (tid + 256 * i);
        int mi = e >> 6, dd = e & 63;
        int tok = g_perm[q0 + mi];
        float4 v = *(const float4*)&qkv[base + (size_t)tok * F3 + h * 64 + dd];
        v.x *= 0.125f; v.y *= 0.125f; v.z *= 0.125f; v.w *= 0.125f;
        float h0 = tobf(v.x), h1 = tobf(v.y), h2 = tobf(v.z), h3 = tobf(v.w);
        uint32_t so = SWZ((uint32_t)(mi * 128 + dd * 2));
        *(uint32_t*)(smc + SM_QH + so)     = pkbf(h0, h1);
        *(uint32_t*)(smc + SM_QH + so + 4) = pkbf(h2, h3);
        *(uint32_t*)(smc + SM_QL + so)     = pkbf(v.x - h0, v.y - h1);
        *(uint32_t*)(smc + SM_QL + so + 4) = pkbf(v.z - h2, v.w - h3);
    }

    // per-thread flash state for rows (warp_m+g) and (warp_m+8+g)
    float M0 = -1e30f, M1 = -1e30f, L0 = 0.f, L1 = 0.f;
    float oacc[8][4];
#pragma unroll
    for (int nt = 0; nt < 8; nt++)
#pragma unroll
        for (int r = 0; r < 4; r++) oacc[nt][r] = 0.f;

    __syncthreads();   // Q staged (also covers first K/V fill ordering below)

    for (int kt = 0; kt < 8; kt++) {
        // ---- fill K tile (64 keys x 64 d), bf16 hi/lo ----
#pragma unroll
        for (int i = 0; i < 4; i++) {
            int e = 4 * (tid + 256 * i);
            int nj = e >> 6, dd = e & 63;
            int tok = g_perm[seg * 512 + kt * 64 + nj];
            float4 v = *(const float4*)&qkv[base + (size_t)tok * F3 + 512 + h * 64 + dd];
            float h0 = tobf(v.x), h1 = tobf(v.y), h2 = tobf(v.z), h3 = tobf(v.w);
            uint32_t so = SWZ((uint32_t)(nj * 128 + dd * 2));
            *(uint32_t*)(smc + SM_KH + so)     = pkbf(h0, h1);
            *(uint32_t*)(smc + SM_KH + so + 4) = pkbf(h2, h3);
            *(uint32_t*)(smc + SM_KL + so)     = pkbf(v.x - h0, v.y - h1);
            *(uint32_t*)(smc + SM_KL + so + 4) = pkbf(v.z - h2, v.w - h3);
        }
        // ---- fill V tile transposed [d][t], bf16 hi/lo ----
#pragma unroll
        for (int i = 0; i < 4; i++) {
            int e = 4 * (tid + 256 * i);
            int tj = e >> 6, dd = e & 63;
            int tok = g_perm[seg * 512 + kt * 64 + tj];
            float4 v = *(const float4*)&qkv[base + (size_t)tok * F3 + 1024 + h * 64 + dd];
            float vv[4] = {v.x, v.y, v.z, v.w};
#pragma unroll
            for (int c = 0; c < 4; c++) {
                uint32_t so = SWZ((uint32_t)((dd + c) * 128 + tj * 2));
                __nv_bfloat16 hb = __float2bfloat16_rn(vv[c]);
                *(__nv_bfloat16*)(smc + SM_VH + so) = hb;
                *(__nv_bfloat16*)(smc + SM_VL + so) =
                    __float2bfloat16_rn(vv[c] - __bfloat162float(hb));
            }
        }
        __syncthreads();

        // ---- S = Q K^T (16m x 64 keys per warp), bf16x3 ----
        float p[8][4];
#pragma unroll
        for (int nt = 0; nt < 8; nt++)
#pragma unroll
            for (int r = 0; r < 4; r++) p[nt][r] = 0.f;

#pragma unroll
        for (int kq = 0; kq < 4; kq++) {
            int l0 = (kq * 32 + t4 * 4) ^ gx;
            int l1 = (kq * 32 + t4 * 4 + 16) ^ gx;
            int rq = (warp_m + g) * 128;
            uint32_t aH[4], aL[4];
            aH[0] = *(const uint32_t*)(smc + SM_QH + rq + l0);
            aH[1] = *(const uint32_t*)(smc + SM_QH + rq + 1024 + l0);
            aH[2] = *(const uint32_t*)(smc + SM_QH + rq + l1);
            aH[3] = *(const uint32_t*)(smc + SM_QH + rq + 1024 + l1);
            aL[0] = *(const uint32_t*)(smc + SM_QL + rq + l0);
            aL[1] = *(const uint32_t*)(smc + SM_QL + rq + 1024 + l0);
            aL[2] = *(const uint32_t*)(smc + SM_QL + rq + l1);
            aL[3] = *(const uint32_t*)(smc + SM_QL + rq + 1024 + l1);
#pragma unroll
            for (int nt = 0; nt < 8; nt++) {
                int rb = (nt * 8 + g) * 128;
                uint32_t bH[2], bL[2];
                bH[0] = *(const uint32_t*)(smc + SM_KH + rb + l0);
                bH[1] = *(const uint32_t*)(smc + SM_KH + rb + l1);
                bL[0] = *(const uint32_t*)(smc + SM_KL + rb + l0);
                bL[1] = *(const uint32_t*)(smc + SM_KL + rb + l1);
                mma16816(p[nt], aH, bH);
                mma16816(p[nt], aH, bL);
                mma16816(p[nt], aL, bH);
            }
        }

        // ---- flash softmax in registers (rows g / g+8, quad reduction) ----
        {
            float m0 = -1e30f, m1 = -1e30f;
#pragma unroll
            for (int nt = 0; nt < 8; nt++) {
                m0 = fmaxf(m0, fmaxf(p[nt][0], p[nt][1]));
                m1 = fmaxf(m1, fmaxf(p[nt][2], p[nt][3]));
            }
            m0 = fmaxf(m0, __shfl_xor_sync(0xffffffffu, m0, 1));
            m0 = fmaxf(m0, __shfl_xor_sync(0xffffffffu, m0, 2));
            m1 = fmaxf(m1, __shfl_xor_sync(0xffffffffu, m1, 1));
            m1 = fmaxf(m1, __shfl_xor_sync(0xffffffffu, m1, 2));
            float mn0 = fmaxf(M0, m0), mn1 = fmaxf(M1, m1);
            float f0 = __expf(M0 - mn0), f1 = __expf(M1 - mn1);
            float s0 = 0.f, s1 = 0.f;
#pragma unroll
            for (int nt = 0; nt < 8; nt++) {
                p[nt][0] = __expf(p[nt][0] - mn0);
                p[nt][1] = __expf(p[nt][1] - mn0);
                p[nt][2] = __expf(p[nt][2] - mn1);
                p[nt][3] = __expf(p[nt][3] - mn1);
                s0 += p[nt][0] + p[nt][1];
                s1 += p[nt][2] + p[nt][3];
            }
            s0 += __shfl_xor_sync(0xffffffffu, s0, 1);
            s0 += __shfl_xor_sync(0xffffffffu, s0, 2);
            s1 += __shfl_xor_sync(0xffffffffu, s1, 1);
            s1 += __shfl_xor_sync(0xffffffffu, s1, 2);
            L0 = L0 * f0 + s0; M0 = mn0;
            L1 = L1 * f1 + s1; M1 = mn1;
#pragma unroll
            for (int nt = 0; nt < 8; nt++) {
                oacc[nt][0] *= f0; oacc[nt][1] *= f0;
                oacc[nt][2] *= f1; oacc[nt][3] *= f1;
            }
        }

        // ---- O += P V : P fragments built in registers from p[][] ----
#pragma unroll
        for (int kq = 0; kq < 4; kq++) {
            // split p into bf16 hi/lo A fragments (k-cols = keys of this kq)
            float h00 = tobf(p[2*kq][0]),   h01 = tobf(p[2*kq][1]);
            float h02 = tobf(p[2*kq][2]),   h03 = tobf(p[2*kq][3]);
            float h10 = tobf(p[2*kq+1][0]), h11 = tobf(p[2*kq+1][1]);
            float h12 = tobf(p[2*kq+1][2]), h13 = tobf(p[2*kq+1][3]);
            uint32_t aH[4], aL[4];
            aH[0] = pkbf(h00, h01);
            aH[1] = pkbf(h02, h03);
            aH[2] = pkbf(h10, h11);
            aH[3] = pkbf(h12, h13);
            aL[0] = pkbf(p[2*kq][0] - h00,   p[2*kq][1] - h01);
            aL[1] = pkbf(p[2*kq][2] - h02,   p[2*kq][3] - h03);
            aL[2] = pkbf(p[2*kq+1][0] - h10, p[2*kq+1][1] - h11);
            aL[3] = pkbf(p[2*kq+1][2] - h12, p[2*kq+1][3] - h13);

            int l0 = (kq * 32 + t4 * 4) ^ gx;
            int l1 = (kq * 32 + t4 * 4 + 16) ^ gx;
#pragma unroll
            for (int nt = 0; nt < 8; nt++) {
                int rb = (nt * 8 + g) * 128;
                uint32_t bH[2], bL[2];
                bH[0] = *(const uint32_t*)(smc + SM_VH + rb + l0);
                bH[1] = *(const uint32_t*)(smc + SM_VH + rb + l1);
                bL[0] = *(const uint32_t*)(smc + SM_VL + rb + l0);
                bL[1] = *(const uint32_t*)(smc + SM_VL + rb + l1);
                mma16816(oacc[nt], aH, bH);
                mma16816(oacc[nt], aH, bL);
                mma16816(oacc[nt], aL, bH);
            }
        }
        __syncthreads();   // protect K/V buffers before next fill
    }

    // ---- normalize + scatter to original token order ----
    {
        float il0 = 1.f / L0, il1 = 1.f / L1;
        int tok0 = g_perm[q0 + warp_m + g];
        int tok1 = g_perm[q0 + warp_m + 8 + g];
        size_t ob0 = ((size_t)b * M_ + tok0) * HD + h * 64;
        size_t ob1 = ((size_t)b * M_ + tok1) * HD + h * 64;
#pragma unroll
        for (int nt = 0; nt < 8; nt++) {
            int ncol = nt * 8 + 2 * t4;
            float2 lo = {oacc[nt][0] * il0, oacc[nt][1] * il0};
            float2 hi = {oacc[nt][2] * il1, oacc[nt][3] * il1};
            *(float2*)&attn[ob0 + ncol] = lo;
            *(float2*)&attn[ob1 + ncol] = hi;
        }
    }
}

// ---------------- launch ----------------
extern "C" void kernel_launch(void* const* d_in, const int* in_sizes, int n_in,
                              void* d_out, int out_size) {
    const float* q     = (const float*)d_in[0];
    const float* w_qkv = (const float*)d_in[3];
    const float* w_out = (const float*)d_in[4];
    float* out = (float*)d_out;

    void *p_x, *p_weff, *p_qkv, *p_attn;
    cudaGetSymbolAddress(&p_x,    g_x);
    cudaGetSymbolAddress(&p_weff, g_weff);
    cudaGetSymbolAddress(&p_qkv,  g_qkv);
    cudaGetSymbolAddress(&p_attn, g_attn);

    cudaFuncSetAttribute(k_attn, cudaFuncAttributeMaxDynamicSharedMemorySize, ATT_SMEM);
    cudaFuncSetAttribute(k_gemm_mma, cudaFuncAttributeMaxDynamicSharedMemorySize, GM_SMEM);

    k_zero_flags<<<64, 256>>>();
    k_hilbert<<<32, 256>>>();
    k_scan<<<1, 256>>>();
    k_rank<<<32, 256>>>();

    k_weff<<<(F3 * D_ + 255) / 256, 256>>>(w_qkv);
    k_mean<<<(B_ * M_ * D_ + 255) / 256, 256>>>(q);

    // GEMM1: qkv[16384,1536] = x[16384,64] * weff[1536,64]^T  (mma.sync bf16x3)
    {
        dim3 grd(F3 / 128, (B_ * M_) / 128);
        k_gemm_mma<<<grd, 256, GM_SMEM>>>((const float*)p_x, (const float*)p_weff,
                                          (float*)p_qkv, F3, D_);
    }

    // fused segment attention (mma.sync bf16x3, register flash softmax)
    k_attn<<<B_ * NSEG * H_ * 4, 256, ATT_SMEM>>>((const float*)p_qkv, (float*)p_attn);

    // GEMM2: out[16384,512] = attn[16384,512] * w_out[512,512]^T  (mma.sync bf16x3)
    {
        dim3 grd(HD / 128, (B_ * M_) / 128);
        k_gemm_mma<<<grd, 256, GM_SMEM>>>((const float*)p_attn, w_out, out, HD, HD);
    }
}

// round 13
// speedup vs baseline: 4.7354x; 1.0588x over previous
#include <cuda_runtime.h>
#include <cuda_bf16.h>
#include <math.h>
#include <stdint.h>

// Problem constants
#define B_   2
#define M_   8192
#define H_   8
#define D_   64
#define HD   512
#define F3   1536
#define NSEG 16

// ---------------- helpers ----------------
__device__ __forceinline__ uint32_t pkbf(float a, float b) {
    __nv_bfloat162 t = __floats2bfloat162_rn(a, b);
    return *reinterpret_cast<uint32_t*>(&t);
}
__device__ __forceinline__ float tobf(float a) {
    return __bfloat162float(__float2bfloat16_rn(a));
}
#define SWZ(o) ((o) ^ (((o) >> 3) & 0x70))

__device__ __forceinline__ void mma16816(float* c, const uint32_t* a, const uint32_t* b) {
    asm volatile(
        "mma.sync.aligned.m16n8k16.row.col.f32.bf16.bf16.f32 "
        "{%0,%1,%2,%3}, {%4,%5,%6,%7}, {%8,%9}, {%0,%1,%2,%3};"
        : "+f"(c[0]), "+f"(c[1]), "+f"(c[2]), "+f"(c[3])
        : "r"(a[0]), "r"(a[1]), "r"(a[2]), "r"(a[3]), "r"(b[0]), "r"(b[1]));
}
__device__ __forceinline__ uint32_t s2u(const void* p) {
    uint32_t a;
    asm("{ .reg .u64 t; cvta.to.shared.u64 t, %1; cvt.u32.u64 %0, t; }" : "=r"(a) : "l"(p));
    return a;
}
__device__ __forceinline__ void cpa16(uint32_t dst, const void* src) {
    asm volatile("cp.async.cg.shared.global [%0], [%1], 16;" :: "r"(dst), "l"(src));
}

// ---------------- device scratch ----------------
__device__ int      g_perm[M_];
__device__ int      g_dval[M_];
__device__ unsigned g_flags[16384];
__device__ unsigned g_psum[16384];
__device__ __nv_bfloat16 g_xh[B_ * M_ * D_];
__device__ __nv_bfloat16 g_xl[B_ * M_ * D_];
__device__ __nv_bfloat16 g_wh[F3 * D_];
__device__ __nv_bfloat16 g_wl[F3 * D_];
__device__ __nv_bfloat16 g_woh[HD * HD];
__device__ __nv_bfloat16 g_wol[HD * HD];
__device__ __nv_bfloat16 g_qh[(size_t)B_ * M_ * F3];
__device__ __nv_bfloat16 g_ql[(size_t)B_ * M_ * F3];
__device__ __nv_bfloat16 g_ah[(size_t)B_ * M_ * HD];
__device__ __nv_bfloat16 g_al[(size_t)B_ * M_ * HD];

// ---------------- fused Hilbert permutation (one block) ----------------
__global__ void k_perm() {
    __shared__ unsigned wsum[32];
    int t = threadIdx.x;
    for (int i = t; i < 16384; i += 1024) g_flags[i] = 0u;
    __syncthreads();
    for (int i = t; i < M_; i += 1024) {
        int x = i & 127, y = i >> 7;
        int d = 0;
        for (int s = 64; s > 0; s >>= 1) {
            int rx = (x & s) ? 1 : 0;
            int ry = (y & s) ? 1 : 0;
            d += s * s * ((3 * rx) ^ ry);
            if (ry == 0) {
                if (rx == 1) { x = s - 1 - x; y = s - 1 - y; }
                int tt = x; x = y; y = tt;
            }
        }
        g_dval[i] = d;
        g_flags[d] = 1u;
    }
    __syncthreads();
    unsigned loc[16], s = 0;
#pragma unroll
    for (int j = 0; j < 16; j++) { loc[j] = g_flags[t * 16 + j]; s += loc[j]; }
    unsigned lane = t & 31, wid = t >> 5;
    unsigned incl = s;
#pragma unroll
    for (int o = 1; o < 32; o <<= 1) {
        unsigned v = __shfl_up_sync(0xffffffffu, incl, o);
        if (lane >= o) incl += v;
    }
    if (lane == 31) wsum[wid] = incl;
    __syncthreads();
    if (wid == 0) {
        unsigned v = wsum[lane];
        unsigned iv = v;
#pragma unroll
        for (int o = 1; o < 32; o <<= 1) {
            unsigned u = __shfl_up_sync(0xffffffffu, iv, o);
            if (lane >= o) iv += u;
        }
        wsum[lane] = iv - v;
    }
    __syncthreads();
    unsigned base = wsum[wid] + incl - s;
#pragma unroll
    for (int j = 0; j < 16; j++) { g_psum[t * 16 + j] = base; base += loc[j]; }
    __syncthreads();
    for (int i = t; i < M_; i += 1024) g_perm[g_psum[g_dval[i]]] = i;
}

// ---------------- producers: split bf16 hi/lo ----------------
__global__ void k_weff(const float* __restrict__ w_qkv) {
    int e = blockIdx.x * 256 + threadIdx.x;
    if (e >= F3 * D_) return;
    int f = e >> 6, d = e & 63;
    float s = 0.f;
#pragma unroll
    for (int h = 0; h < 8; h++) s += w_qkv[f * HD + h * 64 + d];
    float w = 0.125f * s;
    float hh = tobf(w);
    g_wh[e] = __float2bfloat16_rn(w);
    g_wl[e] = __float2bfloat16_rn(w - hh);
}

__global__ void k_mean(const float* __restrict__ q) {
    int e = blockIdx.x * 256 + threadIdx.x;
    if (e >= B_ * M_ * D_) return;
    int row = e >> 6, d = e & 63;
    const float* p = q + (size_t)row * HD + d;
    float s = 0.f;
#pragma unroll
    for (int h = 0; h < 8; h++) s += p[h * 64];
    float hh = tobf(s);
    g_xh[e] = __float2bfloat16_rn(s);
    g_xl[e] = __float2bfloat16_rn(s - hh);
}

__global__ void k_wout(const float* __restrict__ w_out) {
    int e = blockIdx.x * 256 + threadIdx.x;
    if (e >= HD * HD) return;
    float v = w_out[e];
    float hh = tobf(v);
    g_woh[e] = __float2bfloat16_rn(v);
    g_wol[e] = __float2bfloat16_rn(v - hh);
}

// =====================================================================
// GEMM on pre-split bf16 inputs, cp.async double-buffered.
// C[Mr,Nr] = (Ah+Al)[Mr,Kr] * (Bh+Bl)[Nr,Kr]^T, 3-pass mma.
// 128x128 tile, 256 threads, k-chunks of 64. split_out: C as bf16 hi/lo.
// =====================================================================
#define GB_STAGE 65536
__global__ __launch_bounds__(256)
void k_gemm_bf(const __nv_bfloat16* __restrict__ Ah, const __nv_bfloat16* __restrict__ Al,
               const __nv_bfloat16* __restrict__ Bh, const __nv_bfloat16* __restrict__ Bl,
               float* __restrict__ Cf, uint32_t* __restrict__ Ch, uint32_t* __restrict__ Cl,
               int Nr, int Kr, int split_out) {
    extern __shared__ __align__(1024) char smc[];
    uint32_t sb = s2u(smc);
    const int SM_AH = 0, SM_AL = 16384, SM_BH = 32768, SM_BL = 49152;

    int tid = threadIdx.x;
    int wid = tid >> 5, lane = tid & 31;
    int g = lane >> 2, t4 = lane & 3;
    int gx = g << 4;
    int warp_m = (wid >> 2) * 64;
    int warp_n = (wid & 3) * 32;
    int row0 = blockIdx.y * 128, col0 = blockIdx.x * 128;
    int nch = Kr >> 6;

    auto fill = [&](int c, int buf) {
        uint32_t bse = sb + buf * GB_STAGE;
#pragma unroll
        for (int i = 0; i < 4; i++) {
            int id = tid + 256 * i;           // 0..1023
            int r = id >> 3, ch = id & 7;
            uint32_t soff = SWZ((uint32_t)(r * 128 + ch * 16));
            size_t ael = (size_t)(row0 + r) * Kr + c * 64 + ch * 8;
            size_t bel = (size_t)(col0 + r) * Kr + c * 64 + ch * 8;
            cpa16(bse + SM_AH + soff, Ah + ael);
            cpa16(bse + SM_AL + soff, Al + ael);
            cpa16(bse + SM_BH + soff, Bh + bel);
            cpa16(bse + SM_BL + soff, Bl + bel);
        }
        asm volatile("cp.async.commit_group;" ::: "memory");
    };

    float acc[4][4][4];
#pragma unroll
    for (int i = 0; i < 4; i++)
#pragma unroll
        for (int j = 0; j < 4; j++)
#pragma unroll
            for (int r = 0; r < 4; r++) acc[i][j][r] = 0.f;

    fill(0, 0);
    for (int c = 0; c < nch; c++) {
        if (c + 1 < nch) {
            fill(c + 1, (c + 1) & 1);
            asm volatile("cp.async.wait_group 1;" ::: "memory");
        } else {
            asm volatile("cp.async.wait_group 0;" ::: "memory");
        }
        __syncthreads();
        char* smb = smc + (c & 1) * GB_STAGE;

#pragma unroll
        for (int kq = 0; kq < 4; kq++) {
            uint32_t aH[4][4], bH[4][2], bL[4][2], aL[4][4];
            int l0 = (kq * 32 + t4 * 4) ^ gx;
            int l1 = (kq * 32 + t4 * 4 + 16) ^ gx;
#pragma unroll
            for (int mt = 0; mt < 4; mt++) {
                int rb = (warp_m + mt * 16 + g) * 128;
                aH[mt][0] = *(const uint32_t*)(smb + SM_AH + rb + l0);
                aH[mt][1] = *(const uint32_t*)(smb + SM_AH + rb + 1024 + l0);
                aH[mt][2] = *(const uint32_t*)(smb + SM_AH + rb + l1);
                aH[mt][3] = *(const uint32_t*)(smb + SM_AH + rb + 1024 + l1);
            }
#pragma unroll
            for (int nt = 0; nt < 4; nt++) {
                int rb = (warp_n + nt * 8 + g) * 128;
                bH[nt][0] = *(const uint32_t*)(smb + SM_BH + rb + l0);
                bH[nt][1] = *(const uint32_t*)(smb + SM_BH + rb + l1);
            }
#pragma unroll
            for (int mt = 0; mt < 4; mt++)
#pragma unroll
                for (int nt = 0; nt < 4; nt++) mma16816(acc[mt][nt], aH[mt], bH[nt]);

#pragma unroll
            for (int nt = 0; nt < 4; nt++) {
                int rb = (warp_n + nt * 8 + g) * 128;
                bL[nt][0] = *(const uint32_t*)(smb + SM_BL + rb + l0);
                bL[nt][1] = *(const uint32_t*)(smb + SM_BL + rb + l1);
            }
#pragma unroll
            for (int mt = 0; mt < 4; mt++)
#pragma unroll
                for (int nt = 0; nt < 4; nt++) mma16816(acc[mt][nt], aH[mt], bL[nt]);

#pragma unroll
            for (int mt = 0; mt < 4; mt++) {
                int rb = (warp_m + mt * 16 + g) * 128;
                aL[mt][0] = *(const uint32_t*)(smb + SM_AL + rb + l0);
                aL[mt][1] = *(const uint32_t*)(smb + SM_AL + rb + 1024 + l0);
                aL[mt][2] = *(const uint32_t*)(smb + SM_AL + rb + l1);
                aL[mt][3] = *(const uint32_t*)(smb + SM_AL + rb + 1024 + l1);
            }
#pragma unroll
            for (int mt = 0; mt < 4; mt++)
#pragma unroll
                for (int nt = 0; nt < 4; nt++) mma16816(acc[mt][nt], aL[mt], bH[nt]);
        }
        __syncthreads();
    }

    // ---- epilogue ----
#pragma unroll
    for (int mt = 0; mt < 4; mt++) {
        int mrow = row0 + warp_m + mt * 16 + g;
#pragma unroll
        for (int nt = 0; nt < 4; nt++) {
            int ncol = col0 + warp_n + nt * 8 + 2 * t4;
            if (split_out) {
                float a0 = acc[mt][nt][0], a1 = acc[mt][nt][1];
                float h0 = tobf(a0), h1 = tobf(a1);
                size_t i0 = ((size_t)mrow * Nr + ncol) >> 1;
                Ch[i0] = pkbf(a0, a1);
                Cl[i0] = pkbf(a0 - h0, a1 - h1);
                float a2 = acc[mt][nt][2], a3 = acc[mt][nt][3];
                float h2 = tobf(a2), h3 = tobf(a3);
                size_t i1 = ((size_t)(mrow + 8) * Nr + ncol) >> 1;
                Ch[i1] = pkbf(a2, a3);
                Cl[i1] = pkbf(a2 - h2, a3 - h3);
            } else {
                float2 lo = {acc[mt][nt][0], acc[mt][nt][1]};
                float2 hi = {acc[mt][nt][2], acc[mt][nt][3]};
                *(float2*)&Cf[(size_t)mrow * Nr + ncol]       = lo;
                *(float2*)&Cf[(size_t)(mrow + 8) * Nr + ncol] = hi;
            }
        }
    }
}

// =====================================================================
// Fused segment attention on mma.sync bf16x3; inputs pre-split bf16.
// Fills are pure copies. Scores scaled by 0.125 post-mma (exact).
// Output written as split bf16 (g_ah/g_al) for GEMM2.
// =====================================================================
#define ATT_SMEM 65536
__global__ __launch_bounds__(256, 2)
void k_attn() {
    extern __shared__ __align__(1024) char smc[];
    const int SM_QH = 0, SM_QL = 16384;
    const int SM_KH = 32768, SM_KL = 40960;
    const int SM_VH = 49152, SM_VL = 57344;

    int tid = threadIdx.x;
    int wid = tid >> 5, lane = tid & 31;
    int g = lane >> 2, t4 = lane & 3;
    int gx = g << 4;
    int warp_m = wid * 16;

    int bid = blockIdx.x;
    int qc  = bid & 3;
    int h   = (bid >> 2) & 7;
    int seg = (bid >> 5) & 15;
    int b   = bid >> 9;
    size_t qbase = (size_t)b * M_ * F3;
    int q0 = seg * 512 + qc * 128;

    // ---- stage Q (copy from pre-split qkv) ----
#pragma unroll
    for (int i = 0; i < 4; i++) {
        int id = tid + 256 * i;           // 0..1023
        int r = id >> 3, ch = id & 7;
        int tok = g_perm[q0 + r];
        size_t el = qbase + (size_t)tok * F3 + h * 64 + ch * 8;
        uint32_t soff = SWZ((uint32_t)(r * 128 + ch * 16));
        *(uint4*)(smc + SM_QH + soff) = *(const uint4*)(g_qh + el);
        *(uint4*)(smc + SM_QL + soff) = *(const uint4*)(g_ql + el);
    }

    float M0 = -1e30f, M1 = -1e30f, L0 = 0.f, L1 = 0.f;
    float oacc[8][4];
#pragma unroll
    for (int nt = 0; nt < 8; nt++)
#pragma unroll
        for (int r = 0; r < 4; r++) oacc[nt][r] = 0.f;

    __syncthreads();

    for (int kt = 0; kt < 8; kt++) {
        // ---- K tile copy ----
#pragma unroll
        for (int i = 0; i < 2; i++) {
            int id = tid + 256 * i;       // 0..511
            int r = id >> 3, ch = id & 7;
            int tok = g_perm[seg * 512 + kt * 64 + r];
            size_t el = qbase + (size_t)tok * F3 + 512 + h * 64 + ch * 8;
            uint32_t soff = SWZ((uint32_t)(r * 128 + ch * 16));
            *(uint4*)(smc + SM_KH + soff) = *(const uint4*)(g_qh + el);
            *(uint4*)(smc + SM_KL + soff) = *(const uint4*)(g_ql + el);
        }
        // ---- V tile transposed copy [d][t] ----
#pragma unroll
        for (int i = 0; i < 4; i++) {
            int e = 4 * (tid + 256 * i);
            int tj = e >> 6, dd = e & 63;
            int tok = g_perm[seg * 512 + kt * 64 + tj];
            size_t el = qbase + (size_t)tok * F3 + 1024 + h * 64 + dd;
            uint2 vh = *(const uint2*)(g_qh + el);
            uint2 vl = *(const uint2*)(g_ql + el);
            uint32_t s0 = SWZ((uint32_t)((dd + 0) * 128 + tj * 2));
            uint32_t s1 = SWZ((uint32_t)((dd + 1) * 128 + tj * 2));
            uint32_t s2 = SWZ((uint32_t)((dd + 2) * 128 + tj * 2));
            uint32_t s3 = SWZ((uint32_t)((dd + 3) * 128 + tj * 2));
            *(uint16_t*)(smc + SM_VH + s0) = (uint16_t)(vh.x & 0xFFFF);
            *(uint16_t*)(smc + SM_VH + s1) = (uint16_t)(vh.x >> 16);
            *(uint16_t*)(smc + SM_VH + s2) = (uint16_t)(vh.y & 0xFFFF);
            *(uint16_t*)(smc + SM_VH + s3) = (uint16_t)(vh.y >> 16);
            *(uint16_t*)(smc + SM_VL + s0) = (uint16_t)(vl.x & 0xFFFF);
            *(uint16_t*)(smc + SM_VL + s1) = (uint16_t)(vl.x >> 16);
            *(uint16_t*)(smc + SM_VL + s2) = (uint16_t)(vl.y & 0xFFFF);
            *(uint16_t*)(smc + SM_VL + s3) = (uint16_t)(vl.y >> 16);
        }
        __syncthreads();

        // ---- S = Q K^T ----
        float p[8][4];
#pragma unroll
        for (int nt = 0; nt < 8; nt++)
#pragma unroll
            for (int r = 0; r < 4; r++) p[nt][r] = 0.f;

#pragma unroll
        for (int kq = 0; kq < 4; kq++) {
            int l0 = (kq * 32 + t4 * 4) ^ gx;
            int l1 = (kq * 32 + t4 * 4 + 16) ^ gx;
            int rq = (warp_m + g) * 128;
            uint32_t aH[4], aL[4];
            aH[0] = *(const uint32_t*)(smc + SM_QH + rq + l0);
            aH[1] = *(const uint32_t*)(smc + SM_QH + rq + 1024 + l0);
            aH[2] = *(const uint32_t*)(smc + SM_QH + rq + l1);
            aH[3] = *(const uint32_t*)(smc + SM_QH + rq + 1024 + l1);
            aL[0] = *(const uint32_t*)(smc + SM_QL + rq + l0);
            aL[1] = *(const uint32_t*)(smc + SM_QL + rq + 1024 + l0);
            aL[2] = *(const uint32_t*)(smc + SM_QL + rq + l1);
            aL[3] = *(const uint32_t*)(smc + SM_QL + rq + 1024 + l1);
#pragma unroll
            for (int nt = 0; nt < 8; nt++) {
                int rb = (nt * 8 + g) * 128;
                uint32_t bH[2], bL[2];
                bH[0] = *(const uint32_t*)(smc + SM_KH + rb + l0);
                bH[1] = *(const uint32_t*)(smc + SM_KH + rb + l1);
                bL[0] = *(const uint32_t*)(smc + SM_KL + rb + l0);
                bL[1] = *(const uint32_t*)(smc + SM_KL + rb + l1);
                mma16816(p[nt], aH, bH);
                mma16816(p[nt], aH, bL);
                mma16816(p[nt], aL, bH);
            }
        }
        // scores scale (exact power of 2)
#pragma unroll
        for (int nt = 0; nt < 8; nt++)
#pragma unroll
            for (int r = 0; r < 4; r++) p[nt][r] *= 0.125f;

        // ---- flash softmax in registers ----
        {
            float m0 = -1e30f, m1 = -1e30f;
#pragma unroll
            for (int nt = 0; nt < 8; nt++) {
                m0 = fmaxf(m0, fmaxf(p[nt][0], p[nt][1]));
                m1 = fmaxf(m1, fmaxf(p[nt][2], p[nt][3]));
            }
            m0 = fmaxf(m0, __shfl_xor_sync(0xffffffffu, m0, 1));
            m0 = fmaxf(m0, __shfl_xor_sync(0xffffffffu, m0, 2));
            m1 = fmaxf(m1, __shfl_xor_sync(0xffffffffu, m1, 1));
            m1 = fmaxf(m1, __shfl_xor_sync(0xffffffffu, m1, 2));
            float mn0 = fmaxf(M0, m0), mn1 = fmaxf(M1, m1);
            float f0 = __expf(M0 - mn0), f1 = __expf(M1 - mn1);
            float s0 = 0.f, s1 = 0.f;
#pragma unroll
            for (int nt = 0; nt < 8; nt++) {
                p[nt][0] = __expf(p[nt][0] - mn0);
                p[nt][1] = __expf(p[nt][1] - mn0);
                p[nt][2] = __expf(p[nt][2] - mn1);
                p[nt][3] = __expf(p[nt][3] - mn1);
                s0 += p[nt][0] + p[nt][1];
                s1 += p[nt][2] + p[nt][3];
            }
            s0 += __shfl_xor_sync(0xffffffffu, s0, 1);
            s0 += __shfl_xor_sync(0xffffffffu, s0, 2);
            s1 += __shfl_xor_sync(0xffffffffu, s1, 1);
            s1 += __shfl_xor_sync(0xffffffffu, s1, 2);
            L0 = L0 * f0 + s0; M0 = mn0;
            L1 = L1 * f1 + s1; M1 = mn1;
#pragma unroll
            for (int nt = 0; nt < 8; nt++) {
                oacc[nt][0] *= f0; oacc[nt][1] *= f0;
                oacc[nt][2] *= f1; oacc[nt][3] *= f1;
            }
        }

        // ---- O += P V ----
#pragma unroll
        for (int kq = 0; kq < 4; kq++) {
            float h00 = tobf(p[2*kq][0]),   h01 = tobf(p[2*kq][1]);
            float h02 = tobf(p[2*kq][2]),   h03 = tobf(p[2*kq][3]);
            float h10 = tobf(p[2*kq+1][0]), h11 = tobf(p[2*kq+1][1]);
            float h12 = tobf(p[2*kq+1][2]), h13 = tobf(p[2*kq+1][3]);
            uint32_t aH[4], aL[4];
            aH[0] = pkbf(h00, h01);
            aH[1] = pkbf(h02, h03);
            aH[2] = pkbf(h10, h11);
            aH[3] = pkbf(h12, h13);
            aL[0] = pkbf(p[2*kq][0] - h00,   p[2*kq][1] - h01);
            aL[1] = pkbf(p[2*kq][2] - h02,   p[2*kq][3] - h03);
            aL[2] = pkbf(p[2*kq+1][0] - h10, p[2*kq+1][1] - h11);
            aL[3] = pkbf(p[2*kq+1][2] - h12, p[2*kq+1][3] - h13);

            int l0 = (kq * 32 + t4 * 4) ^ gx;
            int l1 = (kq * 32 + t4 * 4 + 16) ^ gx;
#pragma unroll
            for (int nt = 0; nt < 8; nt++) {
                int rb = (nt * 8 + g) * 128;
                uint32_t bH[2], bL[2];
                bH[0] = *(const uint32_t*)(smc + SM_VH + rb + l0);
                bH[1] = *(const uint32_t*)(smc + SM_VH + rb + l1);
                bL[0] = *(const uint32_t*)(smc + SM_VL + rb + l0);
                bL[1] = *(const uint32_t*)(smc + SM_VL + rb + l1);
                mma16816(oacc[nt], aH, bH);
                mma16816(oacc[nt], aH, bL);
                mma16816(oacc[nt], aL, bH);
            }
        }
        __syncthreads();
    }

    // ---- normalize + split-write to g_ah/g_al (original token order) ----
    {
        uint32_t* ah32 = (uint32_t*)g_ah;
        uint32_t* al32 = (uint32_t*)g_al;
        float il0 = 1.f / L0, il1 = 1.f / L1;
        int tok0 = g_perm[q0 + warp_m + g];
        int tok1 = g_perm[q0 + warp_m + 8 + g];
        size_t ob0 = ((size_t)b * M_ + tok0) * HD + h * 64;
        size_t ob1 = ((size_t)b * M_ + tok1) * HD + h * 64;
#pragma unroll
        for (int nt = 0; nt < 8; nt++) {
            int ncol = nt * 8 + 2 * t4;
            float a0 = oacc[nt][0] * il0, a1 = oacc[nt][1] * il0;
            float h0 = tobf(a0), h1 = tobf(a1);
            ah32[(ob0 + ncol) >> 1] = pkbf(a0, a1);
            al32[(ob0 + ncol) >> 1] = pkbf(a0 - h0, a1 - h1);
            float a2 = oacc[nt][2] * il1, a3 = oacc[nt][3] * il1;
            float h2 = tobf(a2), h3 = tobf(a3);
            ah32[(ob1 + ncol) >> 1] = pkbf(a2, a3);
            al32[(ob1 + ncol) >> 1] = pkbf(a2 - h2, a3 - h3);
        }
    }
}

// ---------------- launch ----------------
extern "C" void kernel_launch(void* const* d_in, const int* in_sizes, int n_in,
                              void* d_out, int out_size) {
    const float* q     = (const float*)d_in[0];
    const float* w_qkv = (const float*)d_in[3];
    const float* w_out = (const float*)d_in[4];
    float* out = (float*)d_out;

    void *p_xh, *p_xl, *p_wh, *p_wl, *p_woh, *p_wol, *p_qh, *p_ql, *p_ah, *p_al;
    cudaGetSymbolAddress(&p_xh, g_xh);  cudaGetSymbolAddress(&p_xl, g_xl);
    cudaGetSymbolAddress(&p_wh, g_wh);  cudaGetSymbolAddress(&p_wl, g_wl);
    cudaGetSymbolAddress(&p_woh, g_woh); cudaGetSymbolAddress(&p_wol, g_wol);
    cudaGetSymbolAddress(&p_qh, g_qh);  cudaGetSymbolAddress(&p_ql, g_ql);
    cudaGetSymbolAddress(&p_ah, g_ah);  cudaGetSymbolAddress(&p_al, g_al);

    cudaFuncSetAttribute(k_attn, cudaFuncAttributeMaxDynamicSharedMemorySize, ATT_SMEM);
    cudaFuncSetAttribute(k_gemm_bf, cudaFuncAttributeMaxDynamicSharedMemorySize, 2 * GB_STAGE);

    k_perm<<<1, 1024>>>();
    k_weff<<<(F3 * D_ + 255) / 256, 256>>>(w_qkv);
    k_mean<<<(B_ * M_ * D_ + 255) / 256, 256>>>(q);
    k_wout<<<(HD * HD + 255) / 256, 256>>>(w_out);

    // GEMM1: qkv split = x * weff^T   (K=64 -> one stage, 64KB smem)
    {
        dim3 grd(F3 / 128, (B_ * M_) / 128);
        k_gemm_bf<<<grd, 256, GB_STAGE>>>(
            (const __nv_bfloat16*)p_xh, (const __nv_bfloat16*)p_xl,
            (const __nv_bfloat16*)p_wh, (const __nv_bfloat16*)p_wl,
            nullptr, (uint32_t*)p_qh, (uint32_t*)p_ql, F3, D_, 1);
    }

    // fused segment attention
    k_attn<<<B_ * NSEG * H_ * 4, 256, ATT_SMEM>>>();

    // GEMM2: out = attn_split * w_out^T   (K=512 -> double-buffered, 128KB)
    {
        dim3 grd(HD / 128, (B_ * M_) / 128);
        k_gemm_bf<<<grd, 256, 2 * GB_STAGE>>>(
            (const __nv_bfloat16*)p_ah, (const __nv_bfloat16*)p_al,
            (const __nv_bfloat16*)p_woh, (const __nv_bfloat16*)p_wol,
            out, nullptr, nullptr, HD, HD, 0);
    }
}

// round 16
// speedup vs baseline: 6.0045x; 1.2680x over previous
#include <cuda_runtime.h>
#include <cuda_bf16.h>
#include <math.h>
#include <stdint.h>

// Problem constants
#define B_   2
#define M_   8192
#define H_   8
#define D_   64
#define HD   512
#define F3   1536
#define NSEG 16

// ---------------- helpers ----------------
__device__ __forceinline__ uint32_t pkbf(float a, float b) {
    __nv_bfloat162 t = __floats2bfloat162_rn(a, b);
    return *reinterpret_cast<uint32_t*>(&t);
}
__device__ __forceinline__ float tobf(float a) {
    return __bfloat162float(__float2bfloat16_rn(a));
}
#define SWZ(o) ((o) ^ (((o) >> 3) & 0x70))

__device__ __forceinline__ void mma16816(float* c, const uint32_t* a, const uint32_t* b) {
    asm volatile(
        "mma.sync.aligned.m16n8k16.row.col.f32.bf16.bf16.f32 "
        "{%0,%1,%2,%3}, {%4,%5,%6,%7}, {%8,%9}, {%0,%1,%2,%3};"
        : "+f"(c[0]), "+f"(c[1]), "+f"(c[2]), "+f"(c[3])
        : "r"(a[0]), "r"(a[1]), "r"(a[2]), "r"(a[3]), "r"(b[0]), "r"(b[1]));
}
__device__ __forceinline__ uint32_t s2u(const void* p) {
    uint32_t a;
    asm("{ .reg .u64 t; cvta.to.shared.u64 t, %1; cvt.u32.u64 %0, t; }" : "=r"(a) : "l"(p));
    return a;
}
__device__ __forceinline__ void cpa16(uint32_t dst, const void* src) {
    asm volatile("cp.async.cg.shared.global [%0], [%1], 16;" :: "r"(dst), "l"(src));
}
__device__ __forceinline__ void ldsm4t(uint32_t* r, uint32_t addr) {
    asm volatile("ldmatrix.sync.aligned.m8n8.x4.trans.shared.b16 {%0,%1,%2,%3}, [%4];"
                 : "=r"(r[0]), "=r"(r[1]), "=r"(r[2]), "=r"(r[3]) : "r"(addr));
}

// ---------------- device scratch ----------------
__device__ int      g_perm[M_];
__device__ int      g_dval[M_];
__device__ unsigned g_flags[16384];
__device__ unsigned g_psum[16384];
__device__ __nv_bfloat16 g_xh[B_ * M_ * D_];
__device__ __nv_bfloat16 g_xl[B_ * M_ * D_];
__device__ __nv_bfloat16 g_wh[F3 * D_];
__device__ __nv_bfloat16 g_wl[F3 * D_];
__device__ __nv_bfloat16 g_woh[HD * HD];
__device__ __nv_bfloat16 g_wol[HD * HD];
__device__ __nv_bfloat16 g_qh[(size_t)B_ * M_ * F3];
__device__ __nv_bfloat16 g_ql[(size_t)B_ * M_ * F3];
__device__ __nv_bfloat16 g_ah[(size_t)B_ * M_ * HD];
__device__ __nv_bfloat16 g_al[(size_t)B_ * M_ * HD];

// ---------------- fused Hilbert permutation (one block) ----------------
__global__ void k_perm() {
    __shared__ unsigned wsum[32];
    int t = threadIdx.x;
    for (int i = t; i < 16384; i += 1024) g_flags[i] = 0u;
    __syncthreads();
    for (int i = t; i < M_; i += 1024) {
        int x = i & 127, y = i >> 7;
        int d = 0;
        for (int s = 64; s > 0; s >>= 1) {
            int rx = (x & s) ? 1 : 0;
            int ry = (y & s) ? 1 : 0;
            d += s * s * ((3 * rx) ^ ry);
            if (ry == 0) {
                if (rx == 1) { x = s - 1 - x; y = s - 1 - y; }
                int tt = x; x = y; y = tt;
            }
        }
        g_dval[i] = d;
        g_flags[d] = 1u;
    }
    __syncthreads();
    unsigned loc[16], s = 0;
#pragma unroll
    for (int j = 0; j < 16; j++) { loc[j] = g_flags[t * 16 + j]; s += loc[j]; }
    unsigned lane = t & 31, wid = t >> 5;
    unsigned incl = s;
#pragma unroll
    for (int o = 1; o < 32; o <<= 1) {
        unsigned v = __shfl_up_sync(0xffffffffu, incl, o);
        if (lane >= o) incl += v;
    }
    if (lane == 31) wsum[wid] = incl;
    __syncthreads();
    if (wid == 0) {
        unsigned v = wsum[lane];
        unsigned iv = v;
#pragma unroll
        for (int o = 1; o < 32; o <<= 1) {
            unsigned u = __shfl_up_sync(0xffffffffu, iv, o);
            if (lane >= o) iv += u;
        }
        wsum[lane] = iv - v;
    }
    __syncthreads();
    unsigned base = wsum[wid] + incl - s;
#pragma unroll
    for (int j = 0; j < 16; j++) { g_psum[t * 16 + j] = base; base += loc[j]; }
    __syncthreads();
    for (int i = t; i < M_; i += 1024) g_perm[g_psum[g_dval[i]]] = i;
}

// ---------------- producers: split bf16 hi/lo ----------------
__global__ void k_weff(const float* __restrict__ w_qkv) {
    int e = blockIdx.x * 256 + threadIdx.x;
    if (e >= F3 * D_) return;
    int f = e >> 6, d = e & 63;
    float s = 0.f;
#pragma unroll
    for (int h = 0; h < 8; h++) s += w_qkv[f * HD + h * 64 + d];
    float w = 0.125f * s;
    float hh = tobf(w);
    g_wh[e] = __float2bfloat16_rn(w);
    g_wl[e] = __float2bfloat16_rn(w - hh);
}

__global__ void k_mean(const float* __restrict__ q) {
    int e = blockIdx.x * 256 + threadIdx.x;
    if (e >= B_ * M_ * D_) return;
    int row = e >> 6, d = e & 63;
    const float* p = q + (size_t)row * HD + d;
    float s = 0.f;
#pragma unroll
    for (int h = 0; h < 8; h++) s += p[h * 64];
    float hh = tobf(s);
    g_xh[e] = __float2bfloat16_rn(s);
    g_xl[e] = __float2bfloat16_rn(s - hh);
}

__global__ void k_wout(const float* __restrict__ w_out) {
    int e = blockIdx.x * 256 + threadIdx.x;
    if (e >= HD * HD) return;
    float v = w_out[e];
    float hh = tobf(v);
    g_woh[e] = __float2bfloat16_rn(v);
    g_wol[e] = __float2bfloat16_rn(v - hh);
}

// =====================================================================
// GEMM on pre-split bf16 inputs, cp.async double-buffered (R13, proven).
// =====================================================================
#define GB_STAGE 65536
__global__ __launch_bounds__(256)
void k_gemm_bf(const __nv_bfloat16* __restrict__ Ah, const __nv_bfloat16* __restrict__ Al,
               const __nv_bfloat16* __restrict__ Bh, const __nv_bfloat16* __restrict__ Bl,
               float* __restrict__ Cf, uint32_t* __restrict__ Ch, uint32_t* __restrict__ Cl,
               int Nr, int Kr, int split_out) {
    extern __shared__ __align__(1024) char smc[];
    uint32_t sb = s2u(smc);
    const int SM_AH = 0, SM_AL = 16384, SM_BH = 32768, SM_BL = 49152;

    int tid = threadIdx.x;
    int wid = tid >> 5, lane = tid & 31;
    int g = lane >> 2, t4 = lane & 3;
    int gx = g << 4;
    int warp_m = (wid >> 2) * 64;
    int warp_n = (wid & 3) * 32;
    int row0 = blockIdx.y * 128, col0 = blockIdx.x * 128;
    int nch = Kr >> 6;

    auto fill = [&](int c, int buf) {
        uint32_t bse = sb + buf * GB_STAGE;
#pragma unroll
        for (int i = 0; i < 4; i++) {
            int id = tid + 256 * i;
            int r = id >> 3, ch = id & 7;
            uint32_t soff = SWZ((uint32_t)(r * 128 + ch * 16));
            size_t ael = (size_t)(row0 + r) * Kr + c * 64 + ch * 8;
            size_t bel = (size_t)(col0 + r) * Kr + c * 64 + ch * 8;
            cpa16(bse + SM_AH + soff, Ah + ael);
            cpa16(bse + SM_AL + soff, Al + ael);
            cpa16(bse + SM_BH + soff, Bh + bel);
            cpa16(bse + SM_BL + soff, Bl + bel);
        }
        asm volatile("cp.async.commit_group;" ::: "memory");
    };

    float acc[4][4][4];
#pragma unroll
    for (int i = 0; i < 4; i++)
#pragma unroll
        for (int j = 0; j < 4; j++)
#pragma unroll
            for (int r = 0; r < 4; r++) acc[i][j][r] = 0.f;

    fill(0, 0);
    for (int c = 0; c < nch; c++) {
        if (c + 1 < nch) {
            fill(c + 1, (c + 1) & 1);
            asm volatile("cp.async.wait_group 1;" ::: "memory");
        } else {
            asm volatile("cp.async.wait_group 0;" ::: "memory");
        }
        __syncthreads();
        char* smb = smc + (c & 1) * GB_STAGE;

#pragma unroll
        for (int kq = 0; kq < 4; kq++) {
            uint32_t aH[4][4], bH[4][2], bL[4][2], aL[4][4];
            int l0 = (kq * 32 + t4 * 4) ^ gx;
            int l1 = (kq * 32 + t4 * 4 + 16) ^ gx;
#pragma unroll
            for (int mt = 0; mt < 4; mt++) {
                int rb = (warp_m + mt * 16 + g) * 128;
                aH[mt][0] = *(const uint32_t*)(smb + SM_AH + rb + l0);
                aH[mt][1] = *(const uint32_t*)(smb + SM_AH + rb + 1024 + l0);
                aH[mt][2] = *(const uint32_t*)(smb + SM_AH + rb + l1);
                aH[mt][3] = *(const uint32_t*)(smb + SM_AH + rb + 1024 + l1);
            }
#pragma unroll
            for (int nt = 0; nt < 4; nt++) {
                int rb = (warp_n + nt * 8 + g) * 128;
                bH[nt][0] = *(const uint32_t*)(smb + SM_BH + rb + l0);
                bH[nt][1] = *(const uint32_t*)(smb + SM_BH + rb + l1);
            }
#pragma unroll
            for (int mt = 0; mt < 4; mt++)
#pragma unroll
                for (int nt = 0; nt < 4; nt++) mma16816(acc[mt][nt], aH[mt], bH[nt]);

#pragma unroll
            for (int nt = 0; nt < 4; nt++) {
                int rb = (warp_n + nt * 8 + g) * 128;
                bL[nt][0] = *(const uint32_t*)(smb + SM_BL + rb + l0);
                bL[nt][1] = *(const uint32_t*)(smb + SM_BL + rb + l1);
            }
#pragma unroll
            for (int mt = 0; mt < 4; mt++)
#pragma unroll
                for (int nt = 0; nt < 4; nt++) mma16816(acc[mt][nt], aH[mt], bL[nt]);

#pragma unroll
            for (int mt = 0; mt < 4; mt++) {
                int rb = (warp_m + mt * 16 + g) * 128;
                aL[mt][0] = *(const uint32_t*)(smb + SM_AL + rb + l0);
                aL[mt][1] = *(const uint32_t*)(smb + SM_AL + rb + 1024 + l0);
                aL[mt][2] = *(const uint32_t*)(smb + SM_AL + rb + l1);
                aL[mt][3] = *(const uint32_t*)(smb + SM_AL + rb + 1024 + l1);
            }
#pragma unroll
            for (int mt = 0; mt < 4; mt++)
#pragma unroll
                for (int nt = 0; nt < 4; nt++) mma16816(acc[mt][nt], aL[mt], bH[nt]);
        }
        __syncthreads();
    }

#pragma unroll
    for (int mt = 0; mt < 4; mt++) {
        int mrow = row0 + warp_m + mt * 16 + g;
#pragma unroll
        for (int nt = 0; nt < 4; nt++) {
            int ncol = col0 + warp_n + nt * 8 + 2 * t4;
            if (split_out) {
                float a0 = acc[mt][nt][0], a1 = acc[mt][nt][1];
                float h0 = tobf(a0), h1 = tobf(a1);
                size_t i0 = ((size_t)mrow * Nr + ncol) >> 1;
                Ch[i0] = pkbf(a0, a1);
                Cl[i0] = pkbf(a0 - h0, a1 - h1);
                float a2 = acc[mt][nt][2], a3 = acc[mt][nt][3];
                float h2 = tobf(a2), h3 = tobf(a3);
                size_t i1 = ((size_t)(mrow + 8) * Nr + ncol) >> 1;
                Ch[i1] = pkbf(a2, a3);
                Cl[i1] = pkbf(a2 - h2, a3 - h3);
            } else {
                float2 lo = {acc[mt][nt][0], acc[mt][nt][1]};
                float2 hi = {acc[mt][nt][2], acc[mt][nt][3]};
                *(float2*)&Cf[(size_t)mrow * Nr + ncol]       = lo;
                *(float2*)&Cf[(size_t)(mrow + 8) * Nr + ncol] = hi;
            }
        }
    }
}

// =====================================================================
// Fused segment attention: mma.sync bf16x3, register softmax (no max
// subtraction: |score| <= ~1), V natural layout + ldmatrix.trans,
// cp.async double-buffered K/V tiles.
// smem: Q 32K persistent + 2 stages x (KH/KL/VH/VL 8K each) = 96K.
// =====================================================================
#define ATT_STAGE 32768
#define ATT_SMEM  (32768 + 2 * ATT_STAGE)
__global__ __launch_bounds__(256, 2)
void k_attn() {
    extern __shared__ __align__(1024) char smc[];
    uint32_t sb = s2u(smc);
    const int SM_QH = 0, SM_QL = 16384;
    const int ST0 = 32768;               // stage base
    const int O_KH = 0, O_KL = 8192, O_VH = 16384, O_VL = 24576;

    int tid = threadIdx.x;
    int wid = tid >> 5, lane = tid & 31;
    int g = lane >> 2, t4 = lane & 3;
    int gx = g << 4;
    int warp_m = wid * 16;

    int bid = blockIdx.x;
    int qc  = bid & 3;
    int h   = (bid >> 2) & 7;
    int seg = (bid >> 5) & 15;
    int b   = bid >> 9;
    size_t qbase = (size_t)b * M_ * F3;
    int q0 = seg * 512 + qc * 128;

    // ldmatrix address (V fragment), per lane, function of kq/ntp/stage
    int lq = lane >> 3, lr = lane & 7;

    auto fillKV = [&](int kt, int buf) {
        uint32_t bse = sb + ST0 + buf * ATT_STAGE;
#pragma unroll
        for (int i = 0; i < 2; i++) {
            int id = tid + 256 * i;          // 0..511
            int r = id >> 3, ch = id & 7;
            int tok = g_perm[seg * 512 + kt * 64 + r];
            size_t kel = qbase + (size_t)tok * F3 + 512 + h * 64 + ch * 8;
            size_t vel = kel + 512;
            uint32_t soff = SWZ((uint32_t)(r * 128 + ch * 16));
            cpa16(bse + O_KH + soff, g_qh + kel);
            cpa16(bse + O_KL + soff, g_ql + kel);
            cpa16(bse + O_VH + soff, g_qh + vel);
            cpa16(bse + O_VL + soff, g_ql + vel);
        }
        asm volatile("cp.async.commit_group;" ::: "memory");
    };

    // prefetch tile 0 first so it overlaps the Q staging below
    fillKV(0, 0);

    // ---- stage Q (copy from pre-split qkv) ----
#pragma unroll
    for (int i = 0; i < 4; i++) {
        int id = tid + 256 * i;
        int r = id >> 3, ch = id & 7;
        int tok = g_perm[q0 + r];
        size_t el = qbase + (size_t)tok * F3 + h * 64 + ch * 8;
        uint32_t soff = SWZ((uint32_t)(r * 128 + ch * 16));
        *(uint4*)(smc + SM_QH + soff) = *(const uint4*)(g_qh + el);
        *(uint4*)(smc + SM_QL + soff) = *(const uint4*)(g_ql + el);
    }

    float L0 = 0.f, L1 = 0.f;
    float oacc[8][4];
#pragma unroll
    for (int nt = 0; nt < 8; nt++)
#pragma unroll
        for (int r = 0; r < 4; r++) oacc[nt][r] = 0.f;

    for (int kt = 0; kt < 8; kt++) {
        if (kt + 1 < 8) {
            fillKV(kt + 1, (kt + 1) & 1);
            asm volatile("cp.async.wait_group 1;" ::: "memory");
        } else {
            asm volatile("cp.async.wait_group 0;" ::: "memory");
        }
        __syncthreads();
        uint32_t stg = sb + ST0 + (kt & 1) * ATT_STAGE;
        char* stc = smc + ST0 + (kt & 1) * ATT_STAGE;

        // ---- S = Q K^T ----
        float p[8][4];
#pragma unroll
        for (int nt = 0; nt < 8; nt++)
#pragma unroll
            for (int r = 0; r < 4; r++) p[nt][r] = 0.f;

#pragma unroll
        for (int kq = 0; kq < 4; kq++) {
            int l0 = (kq * 32 + t4 * 4) ^ gx;
            int l1 = (kq * 32 + t4 * 4 + 16) ^ gx;
            int rq = (warp_m + g) * 128;
            uint32_t aH[4], aL[4];
            aH[0] = *(const uint32_t*)(smc + SM_QH + rq + l0);
            aH[1] = *(const uint32_t*)(smc + SM_QH + rq + 1024 + l0);
            aH[2] = *(const uint32_t*)(smc + SM_QH + rq + l1);
            aH[3] = *(const uint32_t*)(smc + SM_QH + rq + 1024 + l1);
            aL[0] = *(const uint32_t*)(smc + SM_QL + rq + l0);
            aL[1] = *(const uint32_t*)(smc + SM_QL + rq + 1024 + l0);
            aL[2] = *(const uint32_t*)(smc + SM_QL + rq + l1);
            aL[3] = *(const uint32_t*)(smc + SM_QL + rq + 1024 + l1);
#pragma unroll
            for (int nt = 0; nt < 8; nt++) {
                int rb = (nt * 8 + g) * 128;
                uint32_t bH[2], bL[2];
                bH[0] = *(const uint32_t*)(stc + O_KH + rb + l0);
                bH[1] = *(const uint32_t*)(stc + O_KH + rb + l1);
                bL[0] = *(const uint32_t*)(stc + O_KL + rb + l0);
                bL[1] = *(const uint32_t*)(stc + O_KL + rb + l1);
                mma16816(p[nt], aH, bH);
                mma16816(p[nt], aH, bL);
                mma16816(p[nt], aL, bH);
            }
        }

        // ---- softmax terms: exp(0.125 * s), running sum only ----
        {
            float s0 = 0.f, s1 = 0.f;
#pragma unroll
            for (int nt = 0; nt < 8; nt++) {
                p[nt][0] = __expf(p[nt][0] * 0.125f);
                p[nt][1] = __expf(p[nt][1] * 0.125f);
                p[nt][2] = __expf(p[nt][2] * 0.125f);
                p[nt][3] = __expf(p[nt][3] * 0.125f);
                s0 += p[nt][0] + p[nt][1];
                s1 += p[nt][2] + p[nt][3];
            }
            s0 += __shfl_xor_sync(0xffffffffu, s0, 1);
            s0 += __shfl_xor_sync(0xffffffffu, s0, 2);
            s1 += __shfl_xor_sync(0xffffffffu, s1, 1);
            s1 += __shfl_xor_sync(0xffffffffu, s1, 2);
            L0 += s0;
            L1 += s1;
        }

        // ---- O += P V : V fragments via ldmatrix.trans ----
#pragma unroll
        for (int kq = 0; kq < 4; kq++) {
            float h00 = tobf(p[2*kq][0]),   h01 = tobf(p[2*kq][1]);
            float h02 = tobf(p[2*kq][2]),   h03 = tobf(p[2*kq][3]);
            float h10 = tobf(p[2*kq+1][0]), h11 = tobf(p[2*kq+1][1]);
            float h12 = tobf(p[2*kq+1][2]), h13 = tobf(p[2*kq+1][3]);
            uint32_t aH[4], aL[4];
            aH[0] = pkbf(h00, h01);
            aH[1] = pkbf(h02, h03);
            aH[2] = pkbf(h10, h11);
            aH[3] = pkbf(h12, h13);
            aL[0] = pkbf(p[2*kq][0] - h00,   p[2*kq][1] - h01);
            aL[1] = pkbf(p[2*kq][2] - h02,   p[2*kq][3] - h03);
            aL[2] = pkbf(p[2*kq+1][0] - h10, p[2*kq+1][1] - h11);
            aL[3] = pkbf(p[2*kq+1][2] - h12, p[2*kq+1][3] - h13);

            int trow = kq * 16 + (lq & 1) * 8 + lr;   // k index (t)
#pragma unroll
            for (int ntp = 0; ntp < 4; ntp++) {
                int ntv = 2 * ntp + (lq >> 1);        // d block (8 cols)
                uint32_t off = SWZ((uint32_t)(trow * 128 + ntv * 16));
                uint32_t bh[4], bl[4];
                ldsm4t(bh, stg + O_VH + off);
                ldsm4t(bl, stg + O_VL + off);
                mma16816(oacc[2*ntp],     aH, bh);
                mma16816(oacc[2*ntp + 1], aH, bh + 2);
                mma16816(oacc[2*ntp],     aH, bl);
                mma16816(oacc[2*ntp + 1], aH, bl + 2);
                mma16816(oacc[2*ntp],     aL, bh);
                mma16816(oacc[2*ntp + 1], aL, bh + 2);
            }
        }
        __syncthreads();
    }

    // ---- normalize + split-write to g_ah/g_al (original token order) ----
    {
        uint32_t* ah32 = (uint32_t*)g_ah;
        uint32_t* al32 = (uint32_t*)g_al;
        float il0 = 1.f / L0, il1 = 1.f / L1;
        int tok0 = g_perm[q0 + warp_m + g];
        int tok1 = g_perm[q0 + warp_m + 8 + g];
        size_t ob0 = ((size_t)b * M_ + tok0) * HD + h * 64;
        size_t ob1 = ((size_t)b * M_ + tok1) * HD + h * 64;
#pragma unroll
        for (int nt = 0; nt < 8; nt++) {
            int ncol = nt * 8 + 2 * t4;
            float a0 = oacc[nt][0] * il0, a1 = oacc[nt][1] * il0;
            float h0 = tobf(a0), h1 = tobf(a1);
            ah32[(ob0 + ncol) >> 1] = pkbf(a0, a1);
            al32[(ob0 + ncol) >> 1] = pkbf(a0 - h0, a1 - h1);
            float a2 = oacc[nt][2] * il1, a3 = oacc[nt][3] * il1;
            float h2 = tobf(a2), h3 = tobf(a3);
            ah32[(ob1 + ncol) >> 1] = pkbf(a2, a3);
            al32[(ob1 + ncol) >> 1] = pkbf(a2 - h2, a3 - h3);
        }
    }
}

// ---------------- launch ----------------
extern "C" void kernel_launch(void* const* d_in, const int* in_sizes, int n_in,
                              void* d_out, int out_size) {
    const float* q     = (const float*)d_in[0];
    const float* w_qkv = (const float*)d_in[3];
    const float* w_out = (const float*)d_in[4];
    float* out = (float*)d_out;

    void *p_xh, *p_xl, *p_wh, *p_wl, *p_woh, *p_wol, *p_qh, *p_ql, *p_ah, *p_al;
    cudaGetSymbolAddress(&p_xh, g_xh);  cudaGetSymbolAddress(&p_xl, g_xl);
    cudaGetSymbolAddress(&p_wh, g_wh);  cudaGetSymbolAddress(&p_wl, g_wl);
    cudaGetSymbolAddress(&p_woh, g_woh); cudaGetSymbolAddress(&p_wol, g_wol);
    cudaGetSymbolAddress(&p_qh, g_qh);  cudaGetSymbolAddress(&p_ql, g_ql);
    cudaGetSymbolAddress(&p_ah, g_ah);  cudaGetSymbolAddress(&p_al, g_al);

    cudaFuncSetAttribute(k_attn, cudaFuncAttributeMaxDynamicSharedMemorySize, ATT_SMEM);
    cudaFuncSetAttribute(k_gemm_bf, cudaFuncAttributeMaxDynamicSharedMemorySize, 2 * GB_STAGE);

    k_perm<<<1, 1024>>>();
    k_weff<<<(F3 * D_ + 255) / 256, 256>>>(w_qkv);
    k_mean<<<(B_ * M_ * D_ + 255) / 256, 256>>>(q);
    k_wout<<<(HD * HD + 255) / 256, 256>>>(w_out);

    // GEMM1: qkv split = x * weff^T
    {
        dim3 grd(F3 / 128, (B_ * M_) / 128);
        k_gemm_bf<<<grd, 256, GB_STAGE>>>(
            (const __nv_bfloat16*)p_xh, (const __nv_bfloat16*)p_xl,
            (const __nv_bfloat16*)p_wh, (const __nv_bfloat16*)p_wl,
            nullptr, (uint32_t*)p_qh, (uint32_t*)p_ql, F3, D_, 1);
    }

    // fused segment attention
    k_attn<<<B_ * NSEG * H_ * 4, 256, ATT_SMEM>>>();

    // GEMM2: out = attn_split * w_out^T
    {
        dim3 grd(HD / 128, (B_ * M_) / 128);
        k_gemm_bf<<<grd, 256, 2 * GB_STAGE>>>(
            (const __nv_bfloat16*)p_ah, (const __nv_bfloat16*)p_al,
            (const __nv_bfloat16*)p_woh, (const __nv_bfloat16*)p_wol,
            out, nullptr, nullptr, HD, HD, 0);
    }
}